// round 8
// baseline (speedup 1.0000x reference)
#include <cuda_runtime.h>
#include <cuda_bf16.h>
#include <cstdint>

#define BATCH 64
#define TT 1024
#define DD 512
#define HH 512
#define J4 2048
#define GRID_R 128        // scan grid (<=148 SMs -> co-resident, barrier safe)

// Scratch (static device memory; no runtime allocation)
__device__ float g_xwt[(size_t)TT * 128 * 64 * 16];   // [t][bu][ab][ut][g]  512 MB
__device__ __nv_bfloat16 g_xb_hi[(size_t)BATCH * TT * DD];  // X bf16 hi [m][k]  64 MB
__device__ __nv_bfloat16 g_xb_lo[(size_t)BATCH * TT * DD];  // X bf16 lo [m][k]  64 MB
__device__ __nv_bfloat16 g_wib_hi[(size_t)J4 * DD];   // [n][k] bf16 hi      2 MB
__device__ __nv_bfloat16 g_wib_lo[(size_t)J4 * DD];   // [n][k] bf16 lo      2 MB
__device__ __nv_bfloat16 g_whB_hi[(size_t)GRID_R * 16 * 512];  // [bu][r][k]  2 MB
__device__ __nv_bfloat16 g_whB_lo[(size_t)GRID_R * 16 * 512];  // [bu][r][k]  2 MB
__device__ __nv_bfloat16 g_hb_hi[2][BATCH * HH];      // h bf16 hi, [b][u]
__device__ __nv_bfloat16 g_hb_lo[2][BATCH * HH];      // h bf16 lo, [b][u]
__device__ unsigned g_arrive[GRID_R * 8];             // padded arrival flags
__device__ unsigned g_rel;

// ---------------------------------------------------------------------------
__device__ __forceinline__ uint32_t smem_u32(const void* p) {
    uint32_t a;
    asm("{ .reg .u64 t; cvta.to.shared.u64 t, %1; cvt.u32.u64 %0, t; }"
        : "=r"(a) : "l"(p));
    return a;
}
#define CP_ASYNC16(dst, src) \
    asm volatile("cp.async.cg.shared.global [%0], [%1], 16;" :: "r"(dst), "l"(src))
#define CP_COMMIT()  asm volatile("cp.async.commit_group;" ::: "memory")
#define CP_WAIT(n)   asm volatile("cp.async.wait_group %0;" :: "n"(n) : "memory")

#define MMA_BF16(d, a0, a1, a2, a3, b0, b1)                                    \
    asm volatile("mma.sync.aligned.m16n8k16.row.col.f32.bf16.bf16.f32 "        \
                 "{%0,%1,%2,%3},{%4,%5,%6,%7},{%8,%9},{%0,%1,%2,%3};"          \
                 : "+f"((d)[0]), "+f"((d)[1]), "+f"((d)[2]), "+f"((d)[3])      \
                 : "r"(a0), "r"(a1), "r"(a2), "r"(a3), "r"(b0), "r"(b1))

__device__ __forceinline__ void st_rel(unsigned* p, unsigned v) {
    asm volatile("st.release.gpu.u32 [%0], %1;" :: "l"(p), "r"(v) : "memory");
}
__device__ __forceinline__ unsigned ld_acq(const unsigned* p) {
    unsigned v;
    asm volatile("ld.acquire.gpu.u32 %0, [%1];" : "=r"(v) : "l"(p) : "memory");
    return v;
}

// ---------------------------------------------------------------------------
__global__ void reset_bar_kernel() {
    if (threadIdx.x < GRID_R * 8) g_arrive[threadIdx.x] = 0u;
    if (threadIdx.x == 0) g_rel = 0u;
}

// X fp32 -> bf16 hi/lo split (same [m][k] layout)
__global__ void pack_x_kernel(const float* __restrict__ X) {
    size_t i = (size_t)blockIdx.x * 256 + threadIdx.x;
    float w = X[i];
    __nv_bfloat16 hi = __float2bfloat16(w);
    __nv_bfloat16 lo = __float2bfloat16(w - __bfloat162float(hi));
    g_xb_hi[i] = hi;
    g_xb_lo[i] = lo;
}

// Wi[k][n] -> bf16 hi/lo split, transposed [n][k]
__global__ void pack_wi_kernel(const float* __restrict__ Wi) {
    int i = blockIdx.x * 256 + threadIdx.x;
    int k = i & 511;
    int n = i >> 9;
    float w = Wi[(size_t)k * J4 + n];
    __nv_bfloat16 hi = __float2bfloat16(w);
    __nv_bfloat16 lo = __float2bfloat16(w - __bfloat162float(hi));
    g_wib_hi[i] = hi;
    g_wib_lo[i] = lo;
}

// Wh -> per-block B-operand slices: g_whB[bu][r=ut*4+g][k], bf16 hi/lo
__global__ void pack_whB_kernel(const float* __restrict__ Wh) {
    int i  = blockIdx.x * 256 + threadIdx.x;
    int k  = i & 511;
    int r  = (i >> 9) & 15;
    int bu = i >> 13;
    int ut = r >> 2, g = r & 3;
    float w = Wh[(size_t)k * J4 + g * 512 + bu * 4 + ut];
    __nv_bfloat16 hi = __float2bfloat16(w);
    __nv_bfloat16 lo = __float2bfloat16(w - __bfloat162float(hi));
    g_whB_hi[i] = hi;
    g_whB_lo[i] = lo;
}

// ---------------------------------------------------------------------------
// HMMA GEMM, cp.async double-buffered: 128x128xK512 (BK=32), 8 warps.
// smem layout per buffer (10240 B each array): AH | AL | BH | BL, x2 buffers.
// ---------------------------------------------------------------------------
#define RSTRIDE 80
#define ARR_SZ (128 * RSTRIDE)     // 10240
#define BUFG_SZ (4 * ARR_SZ)       // 40960
#define SMEM_GEMM (2 * BUFG_SZ)    // 81920

__device__ __forceinline__ void st_xwt(int m, int j, float v) {
    int b = m >> 10, trow = m & 1023, u = j & 511, g = j >> 9;
    g_xwt[(size_t)trow * 131072 + (size_t)(u >> 2) * 1024 + b * 16 + (u & 3) * 4 + g] = v;
}

__global__ __launch_bounds__(256) void gemm_hmma_kernel(const float* __restrict__ bias)
{
    extern __shared__ __align__(16) char sm[];
    const uint32_t sbase = smem_u32(sm);

    const int nBase = blockIdx.x * 128;
    const int mBase = blockIdx.y * 128;
    const int tid = threadIdx.x;
    const int wid = tid >> 5;
    const int lane = tid & 31;
    const int wm = wid >> 2;
    const int wn = wid & 3;
    const int tig = lane & 3;
    const int grp = lane >> 2;

    float acc[4][4][4];
#pragma unroll
    for (int mt = 0; mt < 4; mt++)
#pragma unroll
        for (int nt = 0; nt < 4; nt++)
#pragma unroll
            for (int q = 0; q < 4; q++) acc[mt][nt][q] = 0.f;

    // cp.async fill: per array 512 segs of 16B; 2 per thread
    const int s0 = tid * 2;

#define FILL_CHUNK(buf, ch) do {                                               \
    int k0 = (ch) * 32;                                                        \
    uint32_t db = sbase + (buf) * BUFG_SZ;                                     \
    _Pragma("unroll")                                                          \
    for (int q = 0; q < 2; q++) {                                              \
        int s2 = s0 + q;                                                       \
        int row = s2 >> 2, sg = s2 & 3;                                        \
        uint32_t doff = row * RSTRIDE + sg * 16;                               \
        size_t asrc = ((size_t)(mBase + row) * 512 + k0 + sg * 8) * 2;         \
        size_t bsrc = ((size_t)(nBase + row) * 512 + k0 + sg * 8) * 2;         \
        CP_ASYNC16(db + doff,              (const char*)g_xb_hi + asrc);       \
        CP_ASYNC16(db + ARR_SZ + doff,     (const char*)g_xb_lo + asrc);       \
        CP_ASYNC16(db + 2 * ARR_SZ + doff, (const char*)g_wib_hi + bsrc);      \
        CP_ASYNC16(db + 3 * ARR_SZ + doff, (const char*)g_wib_lo + bsrc);      \
    }                                                                          \
} while (0)

    FILL_CHUNK(0, 0);
    CP_COMMIT();

    for (int ch = 0; ch < 16; ch++) {
        if (ch < 15) {
            FILL_CHUNK((ch + 1) & 1, ch + 1);
            CP_COMMIT();
            CP_WAIT(1);
        } else {
            CP_WAIT(0);
        }
        __syncthreads();

        const char* smAH = sm + (ch & 1) * BUFG_SZ;
        const char* smAL = smAH + ARR_SZ;
        const char* smBH = smAH + 2 * ARR_SZ;
        const char* smBL = smAH + 3 * ARR_SZ;

#pragma unroll
        for (int ks = 0; ks < 2; ks++) {
            const int kb = ks * 16;
            uint32_t bhf[4][2], blf[4][2];
#pragma unroll
            for (int nt = 0; nt < 4; nt++) {
                int row = wn * 32 + nt * 8 + grp;
                int boff = row * RSTRIDE + (kb + tig * 2) * 2;
                bhf[nt][0] = *(uint32_t*)(smBH + boff);
                bhf[nt][1] = *(uint32_t*)(smBH + boff + 16);
                blf[nt][0] = *(uint32_t*)(smBL + boff);
                blf[nt][1] = *(uint32_t*)(smBL + boff + 16);
            }
#pragma unroll
            for (int mt = 0; mt < 4; mt++) {
                int row = wm * 64 + mt * 16 + grp;
                int a0o = row * RSTRIDE + (kb + tig * 2) * 2;
                int a1o = a0o + 8 * RSTRIDE;
                uint32_t ah0 = *(uint32_t*)(smAH + a0o);
                uint32_t ah1 = *(uint32_t*)(smAH + a1o);
                uint32_t ah2 = *(uint32_t*)(smAH + a0o + 16);
                uint32_t ah3 = *(uint32_t*)(smAH + a1o + 16);
                uint32_t al0 = *(uint32_t*)(smAL + a0o);
                uint32_t al1 = *(uint32_t*)(smAL + a1o);
                uint32_t al2 = *(uint32_t*)(smAL + a0o + 16);
                uint32_t al3 = *(uint32_t*)(smAL + a1o + 16);
#pragma unroll
                for (int nt = 0; nt < 4; nt++) {
                    MMA_BF16(acc[mt][nt], ah0, ah1, ah2, ah3, bhf[nt][0], bhf[nt][1]);
                    MMA_BF16(acc[mt][nt], al0, al1, al2, al3, bhf[nt][0], bhf[nt][1]);
                    MMA_BF16(acc[mt][nt], ah0, ah1, ah2, ah3, blf[nt][0], blf[nt][1]);
                }
            }
        }
        __syncthreads();
    }

#pragma unroll
    for (int nt = 0; nt < 4; nt++) {
        int j0 = nBase + wn * 32 + nt * 8 + tig * 2;
        float bb0 = __ldg(&bias[j0]);
        float bb1 = __ldg(&bias[j0 + 1]);
#pragma unroll
        for (int mt = 0; mt < 4; mt++) {
            int m0 = mBase + wm * 64 + mt * 16 + grp;
            st_xwt(m0,     j0,     acc[mt][nt][0] + bb0);
            st_xwt(m0,     j0 + 1, acc[mt][nt][1] + bb1);
            st_xwt(m0 + 8, j0,     acc[mt][nt][2] + bb0);
            st_xwt(m0 + 8, j0 + 1, acc[mt][nt][3] + bb1);
        }
    }
}

// ---------------------------------------------------------------------------
__device__ __forceinline__ float sigf(float x) {
    return 1.0f / (1.0f + __expf(-x));
}
__device__ __forceinline__ float tanhfast(float x) {
    float e = __expf(2.0f * x);
    return 1.0f - 2.0f / (e + 1.0f);
}

// One-hop all-poll barrier: each block stores its own flag; 128 threads of
// EVERY block each poll one flag. Arrival -> visibility = one L2 round trip.
__device__ __forceinline__ void gbar(unsigned idx, int bu, int tid) {
    __syncthreads();
    if (tid == 0) {
        __threadfence();
        st_rel(&g_arrive[bu * 8], idx);
    }
    if (tid < GRID_R) {
        const unsigned* f = &g_arrive[tid * 8];
        while (ld_acq(f) < idx) { }
    }
    __syncthreads();
}

// ---------------------------------------------------------------------------
// HMMA persistent scan (R7 flat-load structure, proven).
// ---------------------------------------------------------------------------
#define HROW 1040
#define HBUF (64 * HROW)                    // 66,560
#define SD_OFF (2 * HBUF)                   // 133,120
#define SDS 20
#define CSH_OFF (SD_OFF + 4 * 64 * SDS * 4) // 153,600
#define SMEM_SCAN (CSH_OFF + 1024)          // 154,624

__global__ __launch_bounds__(512, 1) void lstm_scan_kernel(
    const float* __restrict__ c0, const float* __restrict__ h0,
    float* __restrict__ out)
{
    extern __shared__ __align__(16) char sm[];
    float* sD  = (float*)(sm + SD_OFF);
    float* csh = (float*)(sm + CSH_OFF);
    const uint32_t sbase = smem_u32(sm);

    const int bu = blockIdx.x;
    const int u_base = bu * 4;
    const int tid = threadIdx.x;
    const int lane = tid & 31;
    const int wid = tid >> 5;
    const int grp = lane >> 2;
    const int tig = lane & 3;
    const int mq = wid & 3;            // batch tile (16 batches)
    const int kq = wid >> 2;           // k column (64 units per half)
    const int ab = tid >> 2;           // activation batch (tid<256)
    const int au = tid & 3;            // activation unit

    // ---- Wh B fragments -> registers ----
    uint32_t bH[8][2][2], bL[8][2][2];
    {
        const __nv_bfloat16* baseH = g_whB_hi + (size_t)bu * 16 * 512;
        const __nv_bfloat16* baseL = g_whB_lo + (size_t)bu * 16 * 512;
#pragma unroll
        for (int ks = 0; ks < 8; ks++) {
            int u0 = (ks < 4) ? (kq * 64 + ks * 16) : (256 + kq * 64 + (ks - 4) * 16);
            int k = u0 + tig * 2;
#pragma unroll
            for (int nt = 0; nt < 2; nt++) {
                int r = nt * 8 + grp;
                bH[ks][nt][0] = *(const uint32_t*)(baseH + (size_t)r * 512 + k);
                bH[ks][nt][1] = *(const uint32_t*)(baseH + (size_t)r * 512 + k + 8);
                bL[ks][nt][0] = *(const uint32_t*)(baseL + (size_t)r * 512 + k);
                bL[ks][nt][1] = *(const uint32_t*)(baseL + (size_t)r * 512 + k + 8);
            }
        }
    }

    if (tid < 256) {
        csh[tid] = c0[ab * HH + u_base + au];
        float hv = h0[ab * HH + u_base + au];
        __nv_bfloat16 hi = __float2bfloat16(hv);
        __nv_bfloat16 lo = __float2bfloat16(hv - __bfloat162float(hi));
        g_hb_hi[0][ab * HH + u_base + au] = hi;
        g_hb_lo[0][ab * HH + u_base + au] = lo;
    }
    unsigned bidx = 1;
    gbar(bidx++, bu, tid);

    float* ys = out + 2 * BATCH * HH;

    for (int s = 0; s < TT; s++) {
        const int ph = s & 1;

        float4 xw = make_float4(0.f, 0.f, 0.f, 0.f);
        if (tid < 256)
            xw = __ldg((const float4*)g_xwt +
                       ((size_t)(s * 128 + bu) * 64 + ab) * 4 + au);

        const char* hsH = (const char*)g_hb_hi[ph];
        const char* hsL = (const char*)g_hb_lo[ph];

        // half 0 (u<256): rows' first 512B
#pragma unroll
        for (int q = 0; q < 4; q++) {
            int idx = tid + q * 512;
            int row = idx >> 5, sg = (idx & 31) * 16;
            CP_ASYNC16(sbase + row * HROW + sg,        hsH + row * 1024 + sg);
            CP_ASYNC16(sbase + HBUF + row * HROW + sg, hsL + row * 1024 + sg);
        }
        CP_COMMIT();
        // half 1 (u>=256): rows' second 512B
#pragma unroll
        for (int q = 0; q < 4; q++) {
            int idx = tid + q * 512;
            int row = idx >> 5, sg = (idx & 31) * 16;
            CP_ASYNC16(sbase + row * HROW + 512 + sg,        hsH + row * 1024 + 512 + sg);
            CP_ASYNC16(sbase + HBUF + row * HROW + 512 + sg, hsL + row * 1024 + 512 + sg);
        }
        CP_COMMIT();

        float acc[2][4];
#pragma unroll
        for (int nt = 0; nt < 2; nt++)
#pragma unroll
            for (int q = 0; q < 4; q++) acc[nt][q] = 0.f;

        const char* bufH = sm;
        const char* bufL = sm + HBUF;
        const int arow = mq * 16 + grp;

        CP_WAIT(1);            // half 0 landed
        __syncthreads();
#pragma unroll
        for (int ks = 0; ks < 4; ks++) {
            int col = (kq * 64 + ks * 16 + tig * 2) * 2;
            int aoff = arow * HROW + col;
            uint32_t ah0 = *(const uint32_t*)(bufH + aoff);
            uint32_t ah1 = *(const uint32_t*)(bufH + aoff + 8 * HROW);
            uint32_t ah2 = *(const uint32_t*)(bufH + aoff + 16);
            uint32_t ah3 = *(const uint32_t*)(bufH + aoff + 8 * HROW + 16);
            uint32_t al0 = *(const uint32_t*)(bufL + aoff);
            uint32_t al1 = *(const uint32_t*)(bufL + aoff + 8 * HROW);
            uint32_t al2 = *(const uint32_t*)(bufL + aoff + 16);
            uint32_t al3 = *(const uint32_t*)(bufL + aoff + 8 * HROW + 16);
#pragma unroll
            for (int nt = 0; nt < 2; nt++) {
                MMA_BF16(acc[nt], ah0, ah1, ah2, ah3, bH[ks][nt][0], bH[ks][nt][1]);
                MMA_BF16(acc[nt], al0, al1, al2, al3, bH[ks][nt][0], bH[ks][nt][1]);
                MMA_BF16(acc[nt], ah0, ah1, ah2, ah3, bL[ks][nt][0], bL[ks][nt][1]);
            }
        }
        CP_WAIT(0);            // half 1 landed
        __syncthreads();
#pragma unroll
        for (int ks = 4; ks < 8; ks++) {
            int col = (256 + kq * 64 + (ks - 4) * 16 + tig * 2) * 2;
            int aoff = arow * HROW + col;
            uint32_t ah0 = *(const uint32_t*)(bufH + aoff);
            uint32_t ah1 = *(const uint32_t*)(bufH + aoff + 8 * HROW);
            uint32_t ah2 = *(const uint32_t*)(bufH + aoff + 16);
            uint32_t ah3 = *(const uint32_t*)(bufH + aoff + 8 * HROW + 16);
            uint32_t al0 = *(const uint32_t*)(bufL + aoff);
            uint32_t al1 = *(const uint32_t*)(bufL + aoff + 8 * HROW);
            uint32_t al2 = *(const uint32_t*)(bufL + aoff + 16);
            uint32_t al3 = *(const uint32_t*)(bufL + aoff + 8 * HROW + 16);
#pragma unroll
            for (int nt = 0; nt < 2; nt++) {
                MMA_BF16(acc[nt], ah0, ah1, ah2, ah3, bH[ks][nt][0], bH[ks][nt][1]);
                MMA_BF16(acc[nt], al0, al1, al2, al3, bH[ks][nt][0], bH[ks][nt][1]);
                MMA_BF16(acc[nt], ah0, ah1, ah2, ah3, bL[ks][nt][0], bL[ks][nt][1]);
            }
        }

        // store D partials: sD[kq][b][r], row stride SDS
#pragma unroll
        for (int nt = 0; nt < 2; nt++) {
            *(float2*)&sD[(kq * 64 + mq * 16 + grp) * SDS + nt * 8 + tig * 2] =
                make_float2(acc[nt][0], acc[nt][1]);
            *(float2*)&sD[(kq * 64 + mq * 16 + grp + 8) * SDS + nt * 8 + tig * 2] =
                make_float2(acc[nt][2], acc[nt][3]);
        }
        __syncthreads();

        if (tid < 256) {
            float4 s0 = *(float4*)&sD[(0 * 64 + ab) * SDS + au * 4];
            float4 s1 = *(float4*)&sD[(1 * 64 + ab) * SDS + au * 4];
            float4 s2 = *(float4*)&sD[(2 * 64 + ab) * SDS + au * 4];
            float4 s3 = *(float4*)&sD[(3 * 64 + ab) * SDS + au * 4];
            float si = xw.x + s0.x + s1.x + s2.x + s3.x;
            float sf = xw.y + s0.y + s1.y + s2.y + s3.y;
            float sg = xw.z + s0.z + s1.z + s2.z + s3.z;
            float so = xw.w + s0.w + s1.w + s2.w + s3.w;

            float ig = sigf(si);
            float fg = sigf(sf);
            float gg = tanhfast(sg);
            float og = sigf(so);
            float cold = csh[tid];
            float cnew = fg * cold + ig * gg;
            float hnew = og * tanhfast(cnew);
            csh[tid] = cnew;

            __nv_bfloat16 hi = __float2bfloat16(hnew);
            __nv_bfloat16 lo = __float2bfloat16(hnew - __bfloat162float(hi));
            int uo = ab * HH + u_base + au;
            g_hb_hi[ph ^ 1][uo] = hi;
            g_hb_lo[ph ^ 1][uo] = lo;

            ys[((size_t)ab * TT + s) * HH + u_base + au] = hnew;
            if (s == TT - 1) {
                out[ab * HH + u_base + au] = cnew;                 // cT
                out[BATCH * HH + ab * HH + u_base + au] = hnew;    // hT
            }
        }

        if (s < TT - 1) gbar(bidx++, bu, tid);
    }
}

// ---------------------------------------------------------------------------
extern "C" void kernel_launch(void* const* d_in, const int* in_sizes, int n_in,
                              void* d_out, int out_size) {
    const float* x    = (const float*)d_in[0];   // [64][1024][512]
    const float* c0   = (const float*)d_in[1];   // [64][512]
    const float* h0   = (const float*)d_in[2];   // [64][512]
    const float* Wi   = (const float*)d_in[3];   // [512][2048]
    const float* Wh   = (const float*)d_in[4];   // [512][2048]
    const float* bias = (const float*)d_in[5];   // [2048]
    float* out = (float*)d_out;                  // cT | hT | ys

    cudaFuncSetAttribute(lstm_scan_kernel,
                         cudaFuncAttributeMaxDynamicSharedMemorySize, SMEM_SCAN);
    cudaFuncSetAttribute(gemm_hmma_kernel,
                         cudaFuncAttributeMaxDynamicSharedMemorySize, SMEM_GEMM);

    pack_x_kernel<<<131072, 256>>>(x);
    pack_wi_kernel<<<4096, 256>>>(Wi);
    pack_whB_kernel<<<4096, 256>>>(Wh);
    reset_bar_kernel<<<1, 1024>>>();
    gemm_hmma_kernel<<<dim3(16, 512), 256, SMEM_GEMM>>>(bias);
    lstm_scan_kernel<<<GRID_R, 512, SMEM_SCAN>>>(c0, h0, out);
}

// round 9
// speedup vs baseline: 1.1863x; 1.1863x over previous
#include <cuda_runtime.h>
#include <cuda_bf16.h>
#include <cstdint>

#define BATCH 64
#define TT 1024
#define DD 512
#define HH 512
#define J4 2048
#define GRID_R 128        // scan grid (<=148 SMs -> co-resident, barrier safe)

// Scratch (static device memory; no runtime allocation)
__device__ float g_xwt[(size_t)TT * 128 * 64 * 16];   // [t][bu][ab][ut][g]  512 MB
__device__ __nv_bfloat16 g_xb_hi[(size_t)BATCH * TT * DD];  // X bf16 hi [m][k]  64 MB
__device__ __nv_bfloat16 g_xb_lo[(size_t)BATCH * TT * DD];  // X bf16 lo [m][k]  64 MB
__device__ __nv_bfloat16 g_wib_hi[(size_t)J4 * DD];   // [n][k] bf16 hi      2 MB
__device__ __nv_bfloat16 g_wib_lo[(size_t)J4 * DD];   // [n][k] bf16 lo      2 MB
__device__ __nv_bfloat16 g_whB_hi[(size_t)GRID_R * 16 * 512];  // [bu][r][k]  2 MB
__device__ __nv_bfloat16 g_whB_lo[(size_t)GRID_R * 16 * 512];  // [bu][r][k]  2 MB
__device__ __nv_bfloat16 g_hb_hi[2][BATCH * HH];      // h bf16 hi, [b][u]
__device__ __nv_bfloat16 g_hb_lo[2][BATCH * HH];      // h bf16 lo, [b][u]
__device__ unsigned g_count;
__device__ volatile unsigned g_flag;

// ---------------------------------------------------------------------------
__device__ __forceinline__ uint32_t smem_u32(const void* p) {
    uint32_t a;
    asm("{ .reg .u64 t; cvta.to.shared.u64 t, %1; cvt.u32.u64 %0, t; }"
        : "=r"(a) : "l"(p));
    return a;
}
#define CP_ASYNC16(dst, src) \
    asm volatile("cp.async.cg.shared.global [%0], [%1], 16;" :: "r"(dst), "l"(src))
#define CP_COMMIT()  asm volatile("cp.async.commit_group;" ::: "memory")
#define CP_WAIT(n)   asm volatile("cp.async.wait_group %0;" :: "n"(n) : "memory")

#define MMA_BF16(d, a0, a1, a2, a3, b0, b1)                                    \
    asm volatile("mma.sync.aligned.m16n8k16.row.col.f32.bf16.bf16.f32 "        \
                 "{%0,%1,%2,%3},{%4,%5,%6,%7},{%8,%9},{%0,%1,%2,%3};"          \
                 : "+f"((d)[0]), "+f"((d)[1]), "+f"((d)[2]), "+f"((d)[3])      \
                 : "r"(a0), "r"(a1), "r"(a2), "r"(a3), "r"(b0), "r"(b1))

// ---------------------------------------------------------------------------
__global__ void reset_bar_kernel() { g_count = 0u; g_flag = 0u; }

// X fp32 -> bf16 hi/lo split (same [m][k] layout)
__global__ void pack_x_kernel(const float* __restrict__ X) {
    size_t i = (size_t)blockIdx.x * 256 + threadIdx.x;
    float w = X[i];
    __nv_bfloat16 hi = __float2bfloat16(w);
    __nv_bfloat16 lo = __float2bfloat16(w - __bfloat162float(hi));
    g_xb_hi[i] = hi;
    g_xb_lo[i] = lo;
}

// Wi[k][n] -> bf16 hi/lo split, transposed [n][k]
__global__ void pack_wi_kernel(const float* __restrict__ Wi) {
    int i = blockIdx.x * 256 + threadIdx.x;
    int k = i & 511;
    int n = i >> 9;
    float w = Wi[(size_t)k * J4 + n];
    __nv_bfloat16 hi = __float2bfloat16(w);
    __nv_bfloat16 lo = __float2bfloat16(w - __bfloat162float(hi));
    g_wib_hi[i] = hi;
    g_wib_lo[i] = lo;
}

// Wh -> per-block B-operand slices: g_whB[bu][r=ut*4+g][k], bf16 hi/lo
__global__ void pack_whB_kernel(const float* __restrict__ Wh) {
    int i  = blockIdx.x * 256 + threadIdx.x;
    int k  = i & 511;
    int r  = (i >> 9) & 15;
    int bu = i >> 13;
    int ut = r >> 2, g = r & 3;
    float w = Wh[(size_t)k * J4 + g * 512 + bu * 4 + ut];
    __nv_bfloat16 hi = __float2bfloat16(w);
    __nv_bfloat16 lo = __float2bfloat16(w - __bfloat162float(hi));
    g_whB_hi[i] = hi;
    g_whB_lo[i] = lo;
}

// ---------------------------------------------------------------------------
// HMMA GEMM, cp.async double-buffered: 128x128xK512 (BK=32), 8 warps.
// ---------------------------------------------------------------------------
#define RSTRIDE 80
#define ARR_SZ (128 * RSTRIDE)     // 10240
#define BUFG_SZ (4 * ARR_SZ)       // 40960
#define SMEM_GEMM (2 * BUFG_SZ)    // 81920

__device__ __forceinline__ void st_xwt(int m, int j, float v) {
    int b = m >> 10, trow = m & 1023, u = j & 511, g = j >> 9;
    g_xwt[(size_t)trow * 131072 + (size_t)(u >> 2) * 1024 + b * 16 + (u & 3) * 4 + g] = v;
}

__global__ __launch_bounds__(256) void gemm_hmma_kernel(const float* __restrict__ bias)
{
    extern __shared__ __align__(16) char sm[];
    const uint32_t sbase = smem_u32(sm);

    const int nBase = blockIdx.x * 128;
    const int mBase = blockIdx.y * 128;
    const int tid = threadIdx.x;
    const int wid = tid >> 5;
    const int lane = tid & 31;
    const int wm = wid >> 2;
    const int wn = wid & 3;
    const int tig = lane & 3;
    const int grp = lane >> 2;

    float acc[4][4][4];
#pragma unroll
    for (int mt = 0; mt < 4; mt++)
#pragma unroll
        for (int nt = 0; nt < 4; nt++)
#pragma unroll
            for (int q = 0; q < 4; q++) acc[mt][nt][q] = 0.f;

    const int s0 = tid * 2;

#define FILL_CHUNK(buf, ch) do {                                               \
    int k0 = (ch) * 32;                                                        \
    uint32_t db = sbase + (buf) * BUFG_SZ;                                     \
    _Pragma("unroll")                                                          \
    for (int q = 0; q < 2; q++) {                                              \
        int s2 = s0 + q;                                                       \
        int row = s2 >> 2, sg = s2 & 3;                                        \
        uint32_t doff = row * RSTRIDE + sg * 16;                               \
        size_t asrc = ((size_t)(mBase + row) * 512 + k0 + sg * 8) * 2;         \
        size_t bsrc = ((size_t)(nBase + row) * 512 + k0 + sg * 8) * 2;         \
        CP_ASYNC16(db + doff,              (const char*)g_xb_hi + asrc);       \
        CP_ASYNC16(db + ARR_SZ + doff,     (const char*)g_xb_lo + asrc);       \
        CP_ASYNC16(db + 2 * ARR_SZ + doff, (const char*)g_wib_hi + bsrc);      \
        CP_ASYNC16(db + 3 * ARR_SZ + doff, (const char*)g_wib_lo + bsrc);      \
    }                                                                          \
} while (0)

    FILL_CHUNK(0, 0);
    CP_COMMIT();

    for (int ch = 0; ch < 16; ch++) {
        if (ch < 15) {
            FILL_CHUNK((ch + 1) & 1, ch + 1);
            CP_COMMIT();
            CP_WAIT(1);
        } else {
            CP_WAIT(0);
        }
        __syncthreads();

        const char* smAH = sm + (ch & 1) * BUFG_SZ;
        const char* smAL = smAH + ARR_SZ;
        const char* smBH = smAH + 2 * ARR_SZ;
        const char* smBL = smAH + 3 * ARR_SZ;

#pragma unroll
        for (int ks = 0; ks < 2; ks++) {
            const int kb = ks * 16;
            uint32_t bhf[4][2], blf[4][2];
#pragma unroll
            for (int nt = 0; nt < 4; nt++) {
                int row = wn * 32 + nt * 8 + grp;
                int boff = row * RSTRIDE + (kb + tig * 2) * 2;
                bhf[nt][0] = *(uint32_t*)(smBH + boff);
                bhf[nt][1] = *(uint32_t*)(smBH + boff + 16);
                blf[nt][0] = *(uint32_t*)(smBL + boff);
                blf[nt][1] = *(uint32_t*)(smBL + boff + 16);
            }
#pragma unroll
            for (int mt = 0; mt < 4; mt++) {
                int row = wm * 64 + mt * 16 + grp;
                int a0o = row * RSTRIDE + (kb + tig * 2) * 2;
                int a1o = a0o + 8 * RSTRIDE;
                uint32_t ah0 = *(uint32_t*)(smAH + a0o);
                uint32_t ah1 = *(uint32_t*)(smAH + a1o);
                uint32_t ah2 = *(uint32_t*)(smAH + a0o + 16);
                uint32_t ah3 = *(uint32_t*)(smAH + a1o + 16);
                uint32_t al0 = *(uint32_t*)(smAL + a0o);
                uint32_t al1 = *(uint32_t*)(smAL + a1o);
                uint32_t al2 = *(uint32_t*)(smAL + a0o + 16);
                uint32_t al3 = *(uint32_t*)(smAL + a1o + 16);
#pragma unroll
                for (int nt = 0; nt < 4; nt++) {
                    MMA_BF16(acc[mt][nt], ah0, ah1, ah2, ah3, bhf[nt][0], bhf[nt][1]);
                    MMA_BF16(acc[mt][nt], al0, al1, al2, al3, bhf[nt][0], bhf[nt][1]);
                    MMA_BF16(acc[mt][nt], ah0, ah1, ah2, ah3, blf[nt][0], blf[nt][1]);
                }
            }
        }
        __syncthreads();
    }

#pragma unroll
    for (int nt = 0; nt < 4; nt++) {
        int j0 = nBase + wn * 32 + nt * 8 + tig * 2;
        float bb0 = __ldg(&bias[j0]);
        float bb1 = __ldg(&bias[j0 + 1]);
#pragma unroll
        for (int mt = 0; mt < 4; mt++) {
            int m0 = mBase + wm * 64 + mt * 16 + grp;
            st_xwt(m0,     j0,     acc[mt][nt][0] + bb0);
            st_xwt(m0,     j0 + 1, acc[mt][nt][1] + bb1);
            st_xwt(m0 + 8, j0,     acc[mt][nt][2] + bb0);
            st_xwt(m0 + 8, j0 + 1, acc[mt][nt][3] + bb1);
        }
    }
}

// ---------------------------------------------------------------------------
__device__ __forceinline__ float sigf(float x) {
    return 1.0f / (1.0f + __expf(-x));
}
__device__ __forceinline__ float tanhfast(float x) {
    float e = __expf(2.0f * x);
    return 1.0f - 2.0f / (e + 1.0f);
}

// R6-proven barrier: atomic counter arrive, single volatile flag release,
// nanosleep backoff. One arriving thread per block.
__device__ __forceinline__ void gbar(unsigned idx, int bu, int tid) {
    __syncthreads();
    if (tid == 0) {
        __threadfence();
        unsigned a = atomicAdd(&g_count, 1u) + 1u;
        if (a == idx * GRID_R) {
            g_flag = idx;                         // release
        } else {
            while (g_flag < idx) __nanosleep(32);
            __threadfence();
        }
    }
    __syncthreads();
}

// ---------------------------------------------------------------------------
// HMMA persistent scan (R7 flat-load structure).
// ---------------------------------------------------------------------------
#define HROW 1040
#define HBUF (64 * HROW)                    // 66,560
#define SD_OFF (2 * HBUF)                   // 133,120
#define SDS 20
#define CSH_OFF (SD_OFF + 4 * 64 * SDS * 4) // 153,600
#define SMEM_SCAN (CSH_OFF + 1024)          // 154,624

__global__ __launch_bounds__(512, 1) void lstm_scan_kernel(
    const float* __restrict__ c0, const float* __restrict__ h0,
    float* __restrict__ out)
{
    extern __shared__ __align__(16) char sm[];
    float* sD  = (float*)(sm + SD_OFF);
    float* csh = (float*)(sm + CSH_OFF);
    const uint32_t sbase = smem_u32(sm);

    const int bu = blockIdx.x;
    const int u_base = bu * 4;
    const int tid = threadIdx.x;
    const int lane = tid & 31;
    const int wid = tid >> 5;
    const int grp = lane >> 2;
    const int tig = lane & 3;
    const int mq = wid & 3;            // batch tile (16 batches)
    const int kq = wid >> 2;           // k column (64 units per half)
    const int ab = tid >> 2;           // activation batch (tid<256)
    const int au = tid & 3;            // activation unit

    // ---- Wh B fragments -> registers ----
    uint32_t bH[8][2][2], bL[8][2][2];
    {
        const __nv_bfloat16* baseH = g_whB_hi + (size_t)bu * 16 * 512;
        const __nv_bfloat16* baseL = g_whB_lo + (size_t)bu * 16 * 512;
#pragma unroll
        for (int ks = 0; ks < 8; ks++) {
            int u0 = (ks < 4) ? (kq * 64 + ks * 16) : (256 + kq * 64 + (ks - 4) * 16);
            int k = u0 + tig * 2;
#pragma unroll
            for (int nt = 0; nt < 2; nt++) {
                int r = nt * 8 + grp;
                bH[ks][nt][0] = *(const uint32_t*)(baseH + (size_t)r * 512 + k);
                bH[ks][nt][1] = *(const uint32_t*)(baseH + (size_t)r * 512 + k + 8);
                bL[ks][nt][0] = *(const uint32_t*)(baseL + (size_t)r * 512 + k);
                bL[ks][nt][1] = *(const uint32_t*)(baseL + (size_t)r * 512 + k + 8);
            }
        }
    }

    if (tid < 256) {
        csh[tid] = c0[ab * HH + u_base + au];
        float hv = h0[ab * HH + u_base + au];
        __nv_bfloat16 hi = __float2bfloat16(hv);
        __nv_bfloat16 lo = __float2bfloat16(hv - __bfloat162float(hi));
        g_hb_hi[0][ab * HH + u_base + au] = hi;
        g_hb_lo[0][ab * HH + u_base + au] = lo;
    }
    unsigned bidx = 1;
    gbar(bidx++, bu, tid);

    float* ys = out + 2 * BATCH * HH;

    for (int s = 0; s < TT; s++) {
        const int ph = s & 1;

        float4 xw = make_float4(0.f, 0.f, 0.f, 0.f);
        if (tid < 256)
            xw = __ldg((const float4*)g_xwt +
                       ((size_t)(s * 128 + bu) * 64 + ab) * 4 + au);

        const char* hsH = (const char*)g_hb_hi[ph];
        const char* hsL = (const char*)g_hb_lo[ph];

        // half 0 (u<256): rows' first 512B
#pragma unroll
        for (int q = 0; q < 4; q++) {
            int idx = tid + q * 512;
            int row = idx >> 5, sg = (idx & 31) * 16;
            CP_ASYNC16(sbase + row * HROW + sg,        hsH + row * 1024 + sg);
            CP_ASYNC16(sbase + HBUF + row * HROW + sg, hsL + row * 1024 + sg);
        }
        CP_COMMIT();
        // half 1 (u>=256): rows' second 512B
#pragma unroll
        for (int q = 0; q < 4; q++) {
            int idx = tid + q * 512;
            int row = idx >> 5, sg = (idx & 31) * 16;
            CP_ASYNC16(sbase + row * HROW + 512 + sg,        hsH + row * 1024 + 512 + sg);
            CP_ASYNC16(sbase + HBUF + row * HROW + 512 + sg, hsL + row * 1024 + 512 + sg);
        }
        CP_COMMIT();

        float acc[2][4];
#pragma unroll
        for (int nt = 0; nt < 2; nt++)
#pragma unroll
            for (int q = 0; q < 4; q++) acc[nt][q] = 0.f;

        const char* bufH = sm;
        const char* bufL = sm + HBUF;
        const int arow = mq * 16 + grp;

        CP_WAIT(1);            // half 0 landed
        __syncthreads();
#pragma unroll
        for (int ks = 0; ks < 4; ks++) {
            int col = (kq * 64 + ks * 16 + tig * 2) * 2;
            int aoff = arow * HROW + col;
            uint32_t ah0 = *(const uint32_t*)(bufH + aoff);
            uint32_t ah1 = *(const uint32_t*)(bufH + aoff + 8 * HROW);
            uint32_t ah2 = *(const uint32_t*)(bufH + aoff + 16);
            uint32_t ah3 = *(const uint32_t*)(bufH + aoff + 8 * HROW + 16);
            uint32_t al0 = *(const uint32_t*)(bufL + aoff);
            uint32_t al1 = *(const uint32_t*)(bufL + aoff + 8 * HROW);
            uint32_t al2 = *(const uint32_t*)(bufL + aoff + 16);
            uint32_t al3 = *(const uint32_t*)(bufL + aoff + 8 * HROW + 16);
#pragma unroll
            for (int nt = 0; nt < 2; nt++) {
                MMA_BF16(acc[nt], ah0, ah1, ah2, ah3, bH[ks][nt][0], bH[ks][nt][1]);
                MMA_BF16(acc[nt], al0, al1, al2, al3, bH[ks][nt][0], bH[ks][nt][1]);
                MMA_BF16(acc[nt], ah0, ah1, ah2, ah3, bL[ks][nt][0], bL[ks][nt][1]);
            }
        }
        CP_WAIT(0);            // half 1 landed
        __syncthreads();
#pragma unroll
        for (int ks = 4; ks < 8; ks++) {
            int col = (256 + kq * 64 + (ks - 4) * 16 + tig * 2) * 2;
            int aoff = arow * HROW + col;
            uint32_t ah0 = *(const uint32_t*)(bufH + aoff);
            uint32_t ah1 = *(const uint32_t*)(bufH + aoff + 8 * HROW);
            uint32_t ah2 = *(const uint32_t*)(bufH + aoff + 16);
            uint32_t ah3 = *(const uint32_t*)(bufH + aoff + 8 * HROW + 16);
            uint32_t al0 = *(const uint32_t*)(bufL + aoff);
            uint32_t al1 = *(const uint32_t*)(bufL + aoff + 8 * HROW);
            uint32_t al2 = *(const uint32_t*)(bufL + aoff + 16);
            uint32_t al3 = *(const uint32_t*)(bufL + aoff + 8 * HROW + 16);
#pragma unroll
            for (int nt = 0; nt < 2; nt++) {
                MMA_BF16(acc[nt], ah0, ah1, ah2, ah3, bH[ks][nt][0], bH[ks][nt][1]);
                MMA_BF16(acc[nt], al0, al1, al2, al3, bH[ks][nt][0], bH[ks][nt][1]);
                MMA_BF16(acc[nt], ah0, ah1, ah2, ah3, bL[ks][nt][0], bL[ks][nt][1]);
            }
        }

        // store D partials: sD[kq][b][r], row stride SDS
#pragma unroll
        for (int nt = 0; nt < 2; nt++) {
            *(float2*)&sD[(kq * 64 + mq * 16 + grp) * SDS + nt * 8 + tig * 2] =
                make_float2(acc[nt][0], acc[nt][1]);
            *(float2*)&sD[(kq * 64 + mq * 16 + grp + 8) * SDS + nt * 8 + tig * 2] =
                make_float2(acc[nt][2], acc[nt][3]);
        }
        __syncthreads();

        if (tid < 256) {
            float4 s0 = *(float4*)&sD[(0 * 64 + ab) * SDS + au * 4];
            float4 s1 = *(float4*)&sD[(1 * 64 + ab) * SDS + au * 4];
            float4 s2 = *(float4*)&sD[(2 * 64 + ab) * SDS + au * 4];
            float4 s3 = *(float4*)&sD[(3 * 64 + ab) * SDS + au * 4];
            float si = xw.x + s0.x + s1.x + s2.x + s3.x;
            float sf = xw.y + s0.y + s1.y + s2.y + s3.y;
            float sg = xw.z + s0.z + s1.z + s2.z + s3.z;
            float so = xw.w + s0.w + s1.w + s2.w + s3.w;

            float ig = sigf(si);
            float fg = sigf(sf);
            float gg = tanhfast(sg);
            float og = sigf(so);
            float cold = csh[tid];
            float cnew = fg * cold + ig * gg;
            float hnew = og * tanhfast(cnew);
            csh[tid] = cnew;

            __nv_bfloat16 hi = __float2bfloat16(hnew);
            __nv_bfloat16 lo = __float2bfloat16(hnew - __bfloat162float(hi));
            int uo = ab * HH + u_base + au;
            g_hb_hi[ph ^ 1][uo] = hi;
            g_hb_lo[ph ^ 1][uo] = lo;

            ys[((size_t)ab * TT + s) * HH + u_base + au] = hnew;
            if (s == TT - 1) {
                out[ab * HH + u_base + au] = cnew;                 // cT
                out[BATCH * HH + ab * HH + u_base + au] = hnew;    // hT
            }
        }

        if (s < TT - 1) gbar(bidx++, bu, tid);
    }
}

// ---------------------------------------------------------------------------
extern "C" void kernel_launch(void* const* d_in, const int* in_sizes, int n_in,
                              void* d_out, int out_size) {
    const float* x    = (const float*)d_in[0];   // [64][1024][512]
    const float* c0   = (const float*)d_in[1];   // [64][512]
    const float* h0   = (const float*)d_in[2];   // [64][512]
    const float* Wi   = (const float*)d_in[3];   // [512][2048]
    const float* Wh   = (const float*)d_in[4];   // [512][2048]
    const float* bias = (const float*)d_in[5];   // [2048]
    float* out = (float*)d_out;                  // cT | hT | ys

    cudaFuncSetAttribute(lstm_scan_kernel,
                         cudaFuncAttributeMaxDynamicSharedMemorySize, SMEM_SCAN);
    cudaFuncSetAttribute(gemm_hmma_kernel,
                         cudaFuncAttributeMaxDynamicSharedMemorySize, SMEM_GEMM);

    pack_x_kernel<<<131072, 256>>>(x);
    pack_wi_kernel<<<4096, 256>>>(Wi);
    pack_whB_kernel<<<4096, 256>>>(Wh);
    reset_bar_kernel<<<1, 1>>>();
    gemm_hmma_kernel<<<dim3(16, 512), 256, SMEM_GEMM>>>(bias);
    lstm_scan_kernel<<<GRID_R, 512, SMEM_SCAN>>>(c0, h0, out);
}

// round 10
// speedup vs baseline: 1.3248x; 1.1167x over previous
#include <cuda_runtime.h>
#include <cuda_bf16.h>
#include <cstdint>

#define BATCH 64
#define TT 1024
#define DD 512
#define HH 512
#define J4 2048
#define GRID_R 128        // scan grid (<=148 SMs -> co-resident, barrier safe)

// Scratch (static device memory; no runtime allocation)
__device__ float g_xwt[(size_t)TT * 64 * 64 * 32];    // [t][gu][b][ut][g]   512 MB
__device__ __nv_bfloat16 g_xb_hi[(size_t)BATCH * TT * DD];  // X bf16 hi [m][k]  64 MB
__device__ __nv_bfloat16 g_xb_lo[(size_t)BATCH * TT * DD];  // X bf16 lo [m][k]  64 MB
__device__ __nv_bfloat16 g_wib_hi[(size_t)J4 * DD];   // [n][k] bf16 hi      2 MB
__device__ __nv_bfloat16 g_wib_lo[(size_t)J4 * DD];   // [n][k] bf16 lo      2 MB
__device__ __nv_bfloat16 g_whB_hi[(size_t)64 * 32 * 512];   // [gu][r][k]    2 MB
__device__ __nv_bfloat16 g_whB_lo[(size_t)64 * 32 * 512];   // [gu][r][k]    2 MB
__device__ __nv_bfloat16 g_hb_hi[2][BATCH * HH];      // h bf16 hi, [b][u]
__device__ __nv_bfloat16 g_hb_lo[2][BATCH * HH];      // h bf16 lo, [b][u]
__device__ unsigned g_count;
__device__ volatile unsigned g_flag;

// ---------------------------------------------------------------------------
__device__ __forceinline__ uint32_t smem_u32(const void* p) {
    uint32_t a;
    asm("{ .reg .u64 t; cvta.to.shared.u64 t, %1; cvt.u32.u64 %0, t; }"
        : "=r"(a) : "l"(p));
    return a;
}
#define CP_ASYNC16(dst, src) \
    asm volatile("cp.async.cg.shared.global [%0], [%1], 16;" :: "r"(dst), "l"(src))
#define CP_COMMIT()  asm volatile("cp.async.commit_group;" ::: "memory")
#define CP_WAIT(n)   asm volatile("cp.async.wait_group %0;" :: "n"(n) : "memory")

#define MMA_BF16(d, a0, a1, a2, a3, b0, b1)                                    \
    asm volatile("mma.sync.aligned.m16n8k16.row.col.f32.bf16.bf16.f32 "        \
                 "{%0,%1,%2,%3},{%4,%5,%6,%7},{%8,%9},{%0,%1,%2,%3};"          \
                 : "+f"((d)[0]), "+f"((d)[1]), "+f"((d)[2]), "+f"((d)[3])      \
                 : "r"(a0), "r"(a1), "r"(a2), "r"(a3), "r"(b0), "r"(b1))

// ---------------------------------------------------------------------------
__global__ void reset_bar_kernel() { g_count = 0u; g_flag = 0u; }

// X fp32 -> bf16 hi/lo split (same [m][k] layout)
__global__ void pack_x_kernel(const float* __restrict__ X) {
    size_t i = (size_t)blockIdx.x * 256 + threadIdx.x;
    float w = X[i];
    __nv_bfloat16 hi = __float2bfloat16(w);
    __nv_bfloat16 lo = __float2bfloat16(w - __bfloat162float(hi));
    g_xb_hi[i] = hi;
    g_xb_lo[i] = lo;
}

// Wi[k][n] -> bf16 hi/lo split, transposed [n][k]
__global__ void pack_wi_kernel(const float* __restrict__ Wi) {
    int i = blockIdx.x * 256 + threadIdx.x;
    int k = i & 511;
    int n = i >> 9;
    float w = Wi[(size_t)k * J4 + n];
    __nv_bfloat16 hi = __float2bfloat16(w);
    __nv_bfloat16 lo = __float2bfloat16(w - __bfloat162float(hi));
    g_wib_hi[i] = hi;
    g_wib_lo[i] = lo;
}

// Wh -> per-unit-group B rows: g_whB[gu][r=ut*4+g][k], bf16 hi/lo
__global__ void pack_whB_kernel(const float* __restrict__ Wh) {
    int i  = blockIdx.x * 256 + threadIdx.x;     // 1,048,576 total
    int k  = i & 511;
    int r  = (i >> 9) & 31;
    int gu = i >> 14;
    int ut = r >> 2, g = r & 3;
    float w = Wh[(size_t)k * J4 + g * 512 + gu * 8 + ut];
    __nv_bfloat16 hi = __float2bfloat16(w);
    __nv_bfloat16 lo = __float2bfloat16(w - __bfloat162float(hi));
    g_whB_hi[i] = hi;
    g_whB_lo[i] = lo;
}

// ---------------------------------------------------------------------------
// HMMA GEMM, cp.async double-buffered (R9-proven): 128x128xK512 (BK=32), 8 warps.
// ---------------------------------------------------------------------------
#define RSTRIDE 80
#define ARR_SZ (128 * RSTRIDE)     // 10240
#define BUFG_SZ (4 * ARR_SZ)       // 40960
#define SMEM_GEMM (2 * BUFG_SZ)    // 81920

// m = b*1024 + t ; j = g*512 + u  ->  g_xwt[t][gu][b][ut][g]
__device__ __forceinline__ void st_xwt(int m, int j, float v) {
    int b = m >> 10, t = m & 1023, u = j & 511, g = j >> 9;
    int gu = u >> 3, ut = u & 7;
    g_xwt[(((size_t)t * 64 + gu) * 64 + b) * 32 + ut * 4 + g] = v;
}

__global__ __launch_bounds__(256) void gemm_hmma_kernel(const float* __restrict__ bias)
{
    extern __shared__ __align__(16) char sm[];
    const uint32_t sbase = smem_u32(sm);

    const int nBase = blockIdx.x * 128;
    const int mBase = blockIdx.y * 128;
    const int tid = threadIdx.x;
    const int wid = tid >> 5;
    const int lane = tid & 31;
    const int wm = wid >> 2;
    const int wn = wid & 3;
    const int tig = lane & 3;
    const int grp = lane >> 2;

    float acc[4][4][4];
#pragma unroll
    for (int mt = 0; mt < 4; mt++)
#pragma unroll
        for (int nt = 0; nt < 4; nt++)
#pragma unroll
            for (int q = 0; q < 4; q++) acc[mt][nt][q] = 0.f;

    const int s0 = tid * 2;

#define FILL_CHUNK(buf, ch) do {                                               \
    int k0 = (ch) * 32;                                                        \
    uint32_t db = sbase + (buf) * BUFG_SZ;                                     \
    _Pragma("unroll")                                                          \
    for (int q = 0; q < 2; q++) {                                              \
        int s2 = s0 + q;                                                       \
        int row = s2 >> 2, sg = s2 & 3;                                        \
        uint32_t doff = row * RSTRIDE + sg * 16;                               \
        size_t asrc = ((size_t)(mBase + row) * 512 + k0 + sg * 8) * 2;         \
        size_t bsrc = ((size_t)(nBase + row) * 512 + k0 + sg * 8) * 2;         \
        CP_ASYNC16(db + doff,              (const char*)g_xb_hi + asrc);       \
        CP_ASYNC16(db + ARR_SZ + doff,     (const char*)g_xb_lo + asrc);       \
        CP_ASYNC16(db + 2 * ARR_SZ + doff, (const char*)g_wib_hi + bsrc);      \
        CP_ASYNC16(db + 3 * ARR_SZ + doff, (const char*)g_wib_lo + bsrc);      \
    }                                                                          \
} while (0)

    FILL_CHUNK(0, 0);
    CP_COMMIT();

    for (int ch = 0; ch < 16; ch++) {
        if (ch < 15) {
            FILL_CHUNK((ch + 1) & 1, ch + 1);
            CP_COMMIT();
            CP_WAIT(1);
        } else {
            CP_WAIT(0);
        }
        __syncthreads();

        const char* smAH = sm + (ch & 1) * BUFG_SZ;
        const char* smAL = smAH + ARR_SZ;
        const char* smBH = smAH + 2 * ARR_SZ;
        const char* smBL = smAH + 3 * ARR_SZ;

#pragma unroll
        for (int ks = 0; ks < 2; ks++) {
            const int kb = ks * 16;
            uint32_t bhf[4][2], blf[4][2];
#pragma unroll
            for (int nt = 0; nt < 4; nt++) {
                int row = wn * 32 + nt * 8 + grp;
                int boff = row * RSTRIDE + (kb + tig * 2) * 2;
                bhf[nt][0] = *(uint32_t*)(smBH + boff);
                bhf[nt][1] = *(uint32_t*)(smBH + boff + 16);
                blf[nt][0] = *(uint32_t*)(smBL + boff);
                blf[nt][1] = *(uint32_t*)(smBL + boff + 16);
            }
#pragma unroll
            for (int mt = 0; mt < 4; mt++) {
                int row = wm * 64 + mt * 16 + grp;
                int a0o = row * RSTRIDE + (kb + tig * 2) * 2;
                int a1o = a0o + 8 * RSTRIDE;
                uint32_t ah0 = *(uint32_t*)(smAH + a0o);
                uint32_t ah1 = *(uint32_t*)(smAH + a1o);
                uint32_t ah2 = *(uint32_t*)(smAH + a0o + 16);
                uint32_t ah3 = *(uint32_t*)(smAH + a1o + 16);
                uint32_t al0 = *(uint32_t*)(smAL + a0o);
                uint32_t al1 = *(uint32_t*)(smAL + a1o);
                uint32_t al2 = *(uint32_t*)(smAL + a0o + 16);
                uint32_t al3 = *(uint32_t*)(smAL + a1o + 16);
#pragma unroll
                for (int nt = 0; nt < 4; nt++) {
                    MMA_BF16(acc[mt][nt], ah0, ah1, ah2, ah3, bhf[nt][0], bhf[nt][1]);
                    MMA_BF16(acc[mt][nt], al0, al1, al2, al3, bhf[nt][0], bhf[nt][1]);
                    MMA_BF16(acc[mt][nt], ah0, ah1, ah2, ah3, blf[nt][0], blf[nt][1]);
                }
            }
        }
        __syncthreads();
    }

#pragma unroll
    for (int nt = 0; nt < 4; nt++) {
        int j0 = nBase + wn * 32 + nt * 8 + tig * 2;
        float bb0 = __ldg(&bias[j0]);
        float bb1 = __ldg(&bias[j0 + 1]);
#pragma unroll
        for (int mt = 0; mt < 4; mt++) {
            int m0 = mBase + wm * 64 + mt * 16 + grp;
            st_xwt(m0,     j0,     acc[mt][nt][0] + bb0);
            st_xwt(m0,     j0 + 1, acc[mt][nt][1] + bb1);
            st_xwt(m0 + 8, j0,     acc[mt][nt][2] + bb0);
            st_xwt(m0 + 8, j0 + 1, acc[mt][nt][3] + bb1);
        }
    }
}

// ---------------------------------------------------------------------------
__device__ __forceinline__ float sigf(float x) {
    return 1.0f / (1.0f + __expf(-x));
}
__device__ __forceinline__ float tanhfast(float x) {
    float e = __expf(2.0f * x);
    return 1.0f - 2.0f / (e + 1.0f);
}

// R6-proven barrier: atomic counter arrive, single volatile flag release.
__device__ __forceinline__ void gbar(unsigned idx, int tid) {
    __syncthreads();
    if (tid == 0) {
        __threadfence();
        unsigned a = atomicAdd(&g_count, 1u) + 1u;
        if (a == idx * GRID_R) {
            g_flag = idx;                         // release
        } else {
            while (g_flag < idx) __nanosleep(32);
            __threadfence();
        }
    }
    __syncthreads();
}

// ---------------------------------------------------------------------------
// HMMA persistent scan, 2-D decomposition: 128 blocks = 64 unit-groups x 2
// batch-halves. Block (gu, bh): units [gu*8, gu*8+8) (32 gate-rows), batches
// [bh*32, bh*32+32). Each block loads only ITS 32 batches of h (64 KB/step;
// chip traffic 8 MB/step, halved vs R9).
// 512 threads = 16 warps = 2 mq (16-batch tiles) x 8 kq (64-k slices).
// Per warp: mt=1, nt=4 (32 rows), ks=4; Wh B-fragments in registers (64 regs).
// smem: h hi (32x1040B) | h lo | sD[8][32][36]f32 | csh[256]
// ---------------------------------------------------------------------------
#define HROW 1040
#define HBUF (32 * HROW)                    // 33,280
#define SD_OFF (2 * HBUF)                   // 66,560
#define SDS 36
#define CSH_OFF (SD_OFF + 8 * 32 * SDS * 4) // 103,424
#define SMEM_SCAN (CSH_OFF + 1024)          // 104,448

__global__ __launch_bounds__(512, 1) void lstm_scan_kernel(
    const float* __restrict__ c0, const float* __restrict__ h0,
    float* __restrict__ out)
{
    extern __shared__ __align__(16) char sm[];
    float* sD  = (float*)(sm + SD_OFF);
    float* csh = (float*)(sm + CSH_OFF);
    const uint32_t sbase = smem_u32(sm);

    const int bx = blockIdx.x;
    const int gu = bx >> 1;            // unit group 0..63
    const int bh = bx & 1;             // batch half 0..1
    const int u_base = gu * 8;
    const int b_base = bh * 32;
    const int tid = threadIdx.x;
    const int lane = tid & 31;
    const int wid = tid >> 5;
    const int grp = lane >> 2;
    const int tig = lane & 3;
    const int mq = wid & 1;            // batch tile (16 batches)
    const int kq = wid >> 1;           // k slice (64 k: 32 in each half)
    const int ab = tid >> 3;           // activation local batch (tid<256)
    const int au = tid & 7;            // activation unit 0..7

    // ---- Wh B fragments -> registers (32 rows x warp's 64 k) ----
    // ks 0,1: k = kq*32 + ks*16 (half0) ; ks 2,3: k = 256 + kq*32 + (ks-2)*16
    uint32_t bH[4][4][2], bL[4][4][2];
    {
        const __nv_bfloat16* baseH = g_whB_hi + (size_t)gu * 32 * 512;
        const __nv_bfloat16* baseL = g_whB_lo + (size_t)gu * 32 * 512;
#pragma unroll
        for (int ks = 0; ks < 4; ks++) {
            int kf = (ks < 2) ? (kq * 32 + ks * 16) : (256 + kq * 32 + (ks - 2) * 16);
            kf += tig * 2;
#pragma unroll
            for (int nt = 0; nt < 4; nt++) {
                int r = nt * 8 + grp;
                bH[ks][nt][0] = *(const uint32_t*)(baseH + (size_t)r * 512 + kf);
                bH[ks][nt][1] = *(const uint32_t*)(baseH + (size_t)r * 512 + kf + 8);
                bL[ks][nt][0] = *(const uint32_t*)(baseL + (size_t)r * 512 + kf);
                bL[ks][nt][1] = *(const uint32_t*)(baseL + (size_t)r * 512 + kf + 8);
            }
        }
    }

    if (tid < 256) {
        int bg = b_base + ab;
        csh[tid] = c0[bg * HH + u_base + au];
        float hv = h0[bg * HH + u_base + au];
        __nv_bfloat16 hi = __float2bfloat16(hv);
        __nv_bfloat16 lo = __float2bfloat16(hv - __bfloat162float(hi));
        // bh==0 writes batches 0..31, bh==1 writes 32..63; units overlap across gu
        // -> only gu's own units written here (disjoint ✓)
        g_hb_hi[0][bg * HH + u_base + au] = hi;
        g_hb_lo[0][bg * HH + u_base + au] = lo;
    }
    unsigned bidx = 1;
    gbar(bidx++, tid);

    float* ys = out + 2 * BATCH * HH;

    for (int s = 0; s < TT; s++) {
        const int ph = s & 1;

        float4 xw = make_float4(0.f, 0.f, 0.f, 0.f);
        if (tid < 256)
            xw = __ldg((const float4*)g_xwt +
                       ((((size_t)s * 64 + gu) * 64 + b_base + ab) * 32 + au * 4) / 4);

        const char* hsH = (const char*)g_hb_hi[ph];
        const char* hsL = (const char*)g_hb_lo[ph];

        // half 0 (u<256): first 512B of this block's 32 batch rows
#pragma unroll
        for (int q = 0; q < 2; q++) {
            int idx = tid + q * 512;           // 0..1023
            int row = idx >> 5, sg = (idx & 31) * 16;
            size_t src = (size_t)(b_base + row) * 1024 + sg;
            CP_ASYNC16(sbase + row * HROW + sg,        hsH + src);
            CP_ASYNC16(sbase + HBUF + row * HROW + sg, hsL + src);
        }
        CP_COMMIT();
        // half 1 (u>=256)
#pragma unroll
        for (int q = 0; q < 2; q++) {
            int idx = tid + q * 512;
            int row = idx >> 5, sg = (idx & 31) * 16;
            size_t src = (size_t)(b_base + row) * 1024 + 512 + sg;
            CP_ASYNC16(sbase + row * HROW + 512 + sg,        hsH + src);
            CP_ASYNC16(sbase + HBUF + row * HROW + 512 + sg, hsL + src);
        }
        CP_COMMIT();

        float acc[4][4];   // [nt][q]
#pragma unroll
        for (int nt = 0; nt < 4; nt++)
#pragma unroll
            for (int q = 0; q < 4; q++) acc[nt][q] = 0.f;

        const char* bufH = sm;
        const char* bufL = sm + HBUF;
        const int arow = mq * 16 + grp;

        CP_WAIT(1);            // half 0 landed
        __syncthreads();
#pragma unroll
        for (int ks = 0; ks < 2; ks++) {
            int col = (kq * 32 + ks * 16 + tig * 2) * 2;
            int aoff = arow * HROW + col;
            uint32_t ah0 = *(const uint32_t*)(bufH + aoff);
            uint32_t ah1 = *(const uint32_t*)(bufH + aoff + 8 * HROW);
            uint32_t ah2 = *(const uint32_t*)(bufH + aoff + 16);
            uint32_t ah3 = *(const uint32_t*)(bufH + aoff + 8 * HROW + 16);
            uint32_t al0 = *(const uint32_t*)(bufL + aoff);
            uint32_t al1 = *(const uint32_t*)(bufL + aoff + 8 * HROW);
            uint32_t al2 = *(const uint32_t*)(bufL + aoff + 16);
            uint32_t al3 = *(const uint32_t*)(bufL + aoff + 8 * HROW + 16);
#pragma unroll
            for (int nt = 0; nt < 4; nt++) {
                MMA_BF16(acc[nt], ah0, ah1, ah2, ah3, bH[ks][nt][0], bH[ks][nt][1]);
                MMA_BF16(acc[nt], al0, al1, al2, al3, bH[ks][nt][0], bH[ks][nt][1]);
                MMA_BF16(acc[nt], ah0, ah1, ah2, ah3, bL[ks][nt][0], bL[ks][nt][1]);
            }
        }
        CP_WAIT(0);            // half 1 landed
        __syncthreads();
#pragma unroll
        for (int ks = 2; ks < 4; ks++) {
            int col = (256 + kq * 32 + (ks - 2) * 16 + tig * 2) * 2;
            int aoff = arow * HROW + col;
            uint32_t ah0 = *(const uint32_t*)(bufH + aoff);
            uint32_t ah1 = *(const uint32_t*)(bufH + aoff + 8 * HROW);
            uint32_t ah2 = *(const uint32_t*)(bufH + aoff + 16);
            uint32_t ah3 = *(const uint32_t*)(bufH + aoff + 8 * HROW + 16);
            uint32_t al0 = *(const uint32_t*)(bufL + aoff);
            uint32_t al1 = *(const uint32_t*)(bufL + aoff + 8 * HROW);
            uint32_t al2 = *(const uint32_t*)(bufL + aoff + 16);
            uint32_t al3 = *(const uint32_t*)(bufL + aoff + 8 * HROW + 16);
#pragma unroll
            for (int nt = 0; nt < 4; nt++) {
                MMA_BF16(acc[nt], ah0, ah1, ah2, ah3, bH[ks][nt][0], bH[ks][nt][1]);
                MMA_BF16(acc[nt], al0, al1, al2, al3, bH[ks][nt][0], bH[ks][nt][1]);
                MMA_BF16(acc[nt], ah0, ah1, ah2, ah3, bL[ks][nt][0], bL[ks][nt][1]);
            }
        }

        // store D partials: sD[kq][local b][r], row stride SDS
#pragma unroll
        for (int nt = 0; nt < 4; nt++) {
            *(float2*)&sD[(kq * 32 + mq * 16 + grp) * SDS + nt * 8 + tig * 2] =
                make_float2(acc[nt][0], acc[nt][1]);
            *(float2*)&sD[(kq * 32 + mq * 16 + grp + 8) * SDS + nt * 8 + tig * 2] =
                make_float2(acc[nt][2], acc[nt][3]);
        }
        __syncthreads();

        if (tid < 256) {
            float si = xw.x, sf = xw.y, sg2 = xw.z, so = xw.w;
#pragma unroll
            for (int q = 0; q < 8; q++) {
                float4 s4 = *(float4*)&sD[(q * 32 + ab) * SDS + au * 4];
                si += s4.x; sf += s4.y; sg2 += s4.z; so += s4.w;
            }
            float ig = sigf(si);
            float fg = sigf(sf);
            float gg = tanhfast(sg2);
            float og = sigf(so);
            float cold = csh[tid];
            float cnew = fg * cold + ig * gg;
            float hnew = og * tanhfast(cnew);
            csh[tid] = cnew;

            int bg = b_base + ab;
            __nv_bfloat16 hi = __float2bfloat16(hnew);
            __nv_bfloat16 lo = __float2bfloat16(hnew - __bfloat162float(hi));
            int uo = bg * HH + u_base + au;
            g_hb_hi[ph ^ 1][uo] = hi;
            g_hb_lo[ph ^ 1][uo] = lo;

            ys[((size_t)bg * TT + s) * HH + u_base + au] = hnew;
            if (s == TT - 1) {
                out[bg * HH + u_base + au] = cnew;                 // cT
                out[BATCH * HH + bg * HH + u_base + au] = hnew;    // hT
            }
        }

        if (s < TT - 1) gbar(bidx++, tid);
    }
}

// ---------------------------------------------------------------------------
extern "C" void kernel_launch(void* const* d_in, const int* in_sizes, int n_in,
                              void* d_out, int out_size) {
    const float* x    = (const float*)d_in[0];   // [64][1024][512]
    const float* c0   = (const float*)d_in[1];   // [64][512]
    const float* h0   = (const float*)d_in[2];   // [64][512]
    const float* Wi   = (const float*)d_in[3];   // [512][2048]
    const float* Wh   = (const float*)d_in[4];   // [512][2048]
    const float* bias = (const float*)d_in[5];   // [2048]
    float* out = (float*)d_out;                  // cT | hT | ys

    cudaFuncSetAttribute(lstm_scan_kernel,
                         cudaFuncAttributeMaxDynamicSharedMemorySize, SMEM_SCAN);
    cudaFuncSetAttribute(gemm_hmma_kernel,
                         cudaFuncAttributeMaxDynamicSharedMemorySize, SMEM_GEMM);

    pack_x_kernel<<<131072, 256>>>(x);
    pack_wi_kernel<<<4096, 256>>>(Wi);
    pack_whB_kernel<<<4096, 256>>>(Wh);
    reset_bar_kernel<<<1, 1>>>();
    gemm_hmma_kernel<<<dim3(16, 512), 256, SMEM_GEMM>>>(bias);
    lstm_scan_kernel<<<GRID_R, 512, SMEM_SCAN>>>(c0, h0, out);
}

// round 11
// speedup vs baseline: 1.4219x; 1.0733x over previous
#include <cuda_runtime.h>
#include <cuda_bf16.h>
#include <cstdint>

#define BATCH 64
#define TT 1024
#define DD 512
#define HH 512
#define J4 2048
#define GRID_R 128        // scan grid (<=148 SMs -> co-resident)
#define GRP_N 32          // blocks per barrier group (one batch-quarter)

// Scratch (static device memory; no runtime allocation)
__device__ float g_xwt[(size_t)TT * 32 * 64 * 64];    // [t][gu][b][ut][g]   512 MB
__device__ __nv_bfloat16 g_xb_hi[(size_t)BATCH * TT * DD];  // X bf16 hi [m][k]  64 MB
__device__ __nv_bfloat16 g_xb_lo[(size_t)BATCH * TT * DD];  // X bf16 lo [m][k]  64 MB
__device__ __nv_bfloat16 g_wib_hi[(size_t)J4 * DD];   // [n][k] bf16 hi      2 MB
__device__ __nv_bfloat16 g_wib_lo[(size_t)J4 * DD];   // [n][k] bf16 lo      2 MB
__device__ __nv_bfloat16 g_whB_hi[(size_t)32 * 64 * 512];   // [gu][r][k]    2 MB
__device__ __nv_bfloat16 g_whB_lo[(size_t)32 * 64 * 512];   // [gu][r][k]    2 MB
__device__ __nv_bfloat16 g_hb_hi[2][BATCH * HH];      // h bf16 hi, [b][u]
__device__ __nv_bfloat16 g_hb_lo[2][BATCH * HH];      // h bf16 lo, [b][u]
__device__ unsigned g_cnt4[4 * 32];                   // per-group counters (padded)
__device__ volatile unsigned g_flg4[4 * 32];          // per-group release flags

// ---------------------------------------------------------------------------
__device__ __forceinline__ uint32_t smem_u32(const void* p) {
    uint32_t a;
    asm("{ .reg .u64 t; cvta.to.shared.u64 t, %1; cvt.u32.u64 %0, t; }"
        : "=r"(a) : "l"(p));
    return a;
}
#define CP_ASYNC16(dst, src) \
    asm volatile("cp.async.cg.shared.global [%0], [%1], 16;" :: "r"(dst), "l"(src))
#define CP_COMMIT()  asm volatile("cp.async.commit_group;" ::: "memory")
#define CP_WAIT(n)   asm volatile("cp.async.wait_group %0;" :: "n"(n) : "memory")

#define MMA_BF16(d, a0, a1, a2, a3, b0, b1)                                    \
    asm volatile("mma.sync.aligned.m16n8k16.row.col.f32.bf16.bf16.f32 "        \
                 "{%0,%1,%2,%3},{%4,%5,%6,%7},{%8,%9},{%0,%1,%2,%3};"          \
                 : "+f"((d)[0]), "+f"((d)[1]), "+f"((d)[2]), "+f"((d)[3])      \
                 : "r"(a0), "r"(a1), "r"(a2), "r"(a3), "r"(b0), "r"(b1))

// ---------------------------------------------------------------------------
__global__ void reset_bar_kernel() {
    g_cnt4[threadIdx.x] = 0u;
    g_flg4[threadIdx.x] = 0u;
}

// X fp32 -> bf16 hi/lo split (same [m][k] layout)
__global__ void pack_x_kernel(const float* __restrict__ X) {
    size_t i = (size_t)blockIdx.x * 256 + threadIdx.x;
    float w = X[i];
    __nv_bfloat16 hi = __float2bfloat16(w);
    __nv_bfloat16 lo = __float2bfloat16(w - __bfloat162float(hi));
    g_xb_hi[i] = hi;
    g_xb_lo[i] = lo;
}

// Wi[k][n] -> bf16 hi/lo split, transposed [n][k]
__global__ void pack_wi_kernel(const float* __restrict__ Wi) {
    int i = blockIdx.x * 256 + threadIdx.x;
    int k = i & 511;
    int n = i >> 9;
    float w = Wi[(size_t)k * J4 + n];
    __nv_bfloat16 hi = __float2bfloat16(w);
    __nv_bfloat16 lo = __float2bfloat16(w - __bfloat162float(hi));
    g_wib_hi[i] = hi;
    g_wib_lo[i] = lo;
}

// Wh -> per-unit-group B rows: g_whB[gu][r=ut*4+g][k], gu has 16 units (64 rows)
__global__ void pack_whB_kernel(const float* __restrict__ Wh) {
    int i  = blockIdx.x * 256 + threadIdx.x;     // 1,048,576 total
    int k  = i & 511;
    int r  = (i >> 9) & 63;
    int gu = i >> 15;
    int ut = r >> 2, g = r & 3;
    float w = Wh[(size_t)k * J4 + g * 512 + gu * 16 + ut];
    __nv_bfloat16 hi = __float2bfloat16(w);
    __nv_bfloat16 lo = __float2bfloat16(w - __bfloat162float(hi));
    g_whB_hi[i] = hi;
    g_whB_lo[i] = lo;
}

// ---------------------------------------------------------------------------
// HMMA GEMM, cp.async double-buffered (proven): 128x128xK512 (BK=32), 8 warps.
// ---------------------------------------------------------------------------
#define RSTRIDE 80
#define ARR_SZ (128 * RSTRIDE)     // 10240
#define BUFG_SZ (4 * ARR_SZ)       // 40960
#define SMEM_GEMM (2 * BUFG_SZ)    // 81920

// m = b*1024 + t ; j = g*512 + u  ->  g_xwt[t][gu][b][ut][g]
__device__ __forceinline__ void st_xwt(int m, int j, float v) {
    int b = m >> 10, t = m & 1023, u = j & 511, g = j >> 9;
    int gu = u >> 4, ut = u & 15;
    g_xwt[((((size_t)t * 32 + gu) * 64 + b) * 16 + ut) * 4 + g] = v;
}

__global__ __launch_bounds__(256) void gemm_hmma_kernel(const float* __restrict__ bias)
{
    extern __shared__ __align__(16) char sm[];
    const uint32_t sbase = smem_u32(sm);

    const int nBase = blockIdx.x * 128;
    const int mBase = blockIdx.y * 128;
    const int tid = threadIdx.x;
    const int wid = tid >> 5;
    const int lane = tid & 31;
    const int wm = wid >> 2;
    const int wn = wid & 3;
    const int tig = lane & 3;
    const int grp = lane >> 2;

    float acc[4][4][4];
#pragma unroll
    for (int mt = 0; mt < 4; mt++)
#pragma unroll
        for (int nt = 0; nt < 4; nt++)
#pragma unroll
            for (int q = 0; q < 4; q++) acc[mt][nt][q] = 0.f;

    const int s0 = tid * 2;

#define FILL_CHUNK(buf, ch) do {                                               \
    int k0 = (ch) * 32;                                                        \
    uint32_t db = sbase + (buf) * BUFG_SZ;                                     \
    _Pragma("unroll")                                                          \
    for (int q = 0; q < 2; q++) {                                              \
        int s2 = s0 + q;                                                       \
        int row = s2 >> 2, sg = s2 & 3;                                        \
        uint32_t doff = row * RSTRIDE + sg * 16;                               \
        size_t asrc = ((size_t)(mBase + row) * 512 + k0 + sg * 8) * 2;         \
        size_t bsrc = ((size_t)(nBase + row) * 512 + k0 + sg * 8) * 2;         \
        CP_ASYNC16(db + doff,              (const char*)g_xb_hi + asrc);       \
        CP_ASYNC16(db + ARR_SZ + doff,     (const char*)g_xb_lo + asrc);       \
        CP_ASYNC16(db + 2 * ARR_SZ + doff, (const char*)g_wib_hi + bsrc);      \
        CP_ASYNC16(db + 3 * ARR_SZ + doff, (const char*)g_wib_lo + bsrc);      \
    }                                                                          \
} while (0)

    FILL_CHUNK(0, 0);
    CP_COMMIT();

    for (int ch = 0; ch < 16; ch++) {
        if (ch < 15) {
            FILL_CHUNK((ch + 1) & 1, ch + 1);
            CP_COMMIT();
            CP_WAIT(1);
        } else {
            CP_WAIT(0);
        }
        __syncthreads();

        const char* smAH = sm + (ch & 1) * BUFG_SZ;
        const char* smAL = smAH + ARR_SZ;
        const char* smBH = smAH + 2 * ARR_SZ;
        const char* smBL = smAH + 3 * ARR_SZ;

#pragma unroll
        for (int ks = 0; ks < 2; ks++) {
            const int kb = ks * 16;
            uint32_t bhf[4][2], blf[4][2];
#pragma unroll
            for (int nt = 0; nt < 4; nt++) {
                int row = wn * 32 + nt * 8 + grp;
                int boff = row * RSTRIDE + (kb + tig * 2) * 2;
                bhf[nt][0] = *(uint32_t*)(smBH + boff);
                bhf[nt][1] = *(uint32_t*)(smBH + boff + 16);
                blf[nt][0] = *(uint32_t*)(smBL + boff);
                blf[nt][1] = *(uint32_t*)(smBL + boff + 16);
            }
#pragma unroll
            for (int mt = 0; mt < 4; mt++) {
                int row = wm * 64 + mt * 16 + grp;
                int a0o = row * RSTRIDE + (kb + tig * 2) * 2;
                int a1o = a0o + 8 * RSTRIDE;
                uint32_t ah0 = *(uint32_t*)(smAH + a0o);
                uint32_t ah1 = *(uint32_t*)(smAH + a1o);
                uint32_t ah2 = *(uint32_t*)(smAH + a0o + 16);
                uint32_t ah3 = *(uint32_t*)(smAH + a1o + 16);
                uint32_t al0 = *(uint32_t*)(smAL + a0o);
                uint32_t al1 = *(uint32_t*)(smAL + a1o);
                uint32_t al2 = *(uint32_t*)(smAL + a0o + 16);
                uint32_t al3 = *(uint32_t*)(smAL + a1o + 16);
#pragma unroll
                for (int nt = 0; nt < 4; nt++) {
                    MMA_BF16(acc[mt][nt], ah0, ah1, ah2, ah3, bhf[nt][0], bhf[nt][1]);
                    MMA_BF16(acc[mt][nt], al0, al1, al2, al3, bhf[nt][0], bhf[nt][1]);
                    MMA_BF16(acc[mt][nt], ah0, ah1, ah2, ah3, blf[nt][0], blf[nt][1]);
                }
            }
        }
        __syncthreads();
    }

#pragma unroll
    for (int nt = 0; nt < 4; nt++) {
        int j0 = nBase + wn * 32 + nt * 8 + tig * 2;
        float bb0 = __ldg(&bias[j0]);
        float bb1 = __ldg(&bias[j0 + 1]);
#pragma unroll
        for (int mt = 0; mt < 4; mt++) {
            int m0 = mBase + wm * 64 + mt * 16 + grp;
            st_xwt(m0,     j0,     acc[mt][nt][0] + bb0);
            st_xwt(m0,     j0 + 1, acc[mt][nt][1] + bb1);
            st_xwt(m0 + 8, j0,     acc[mt][nt][2] + bb0);
            st_xwt(m0 + 8, j0 + 1, acc[mt][nt][3] + bb1);
        }
    }
}

// ---------------------------------------------------------------------------
__device__ __forceinline__ float sigf(float x) {
    return 1.0f / (1.0f + __expf(-x));
}
__device__ __forceinline__ float tanhfast(float x) {
    float e = __expf(2.0f * x);
    return 1.0f - 2.0f / (e + 1.0f);
}

// Per-group barrier (32 blocks sharing one batch-quarter). Atomic counter +
// volatile flag release, nanosleep backoff (R6-proven scheme, group-scoped).
__device__ __forceinline__ void gbar(unsigned idx, int bq, int tid) {
    __syncthreads();
    if (tid == 0) {
        __threadfence();
        unsigned a = atomicAdd(&g_cnt4[bq * 32], 1u) + 1u;
        if (a == idx * GRP_N) {
            g_flg4[bq * 32] = idx;                // release
        } else {
            while (g_flg4[bq * 32] < idx) __nanosleep(20);
            __threadfence();
        }
    }
    __syncthreads();
}

// ---------------------------------------------------------------------------
// HMMA persistent scan, 2-D decomposition: 128 blocks = 32 unit-groups x 4
// batch-quarters. Block (gu, bq): units [gu*16, +16) (64 gate rows), batches
// [bq*16, +16). h load: 32 KB/step/block -> 4 MB chip. Barrier: group-local.
// 512 threads = 16 warps = 2 nw (32-row tiles) x 8 kq (64-k slices).
// Per warp: 4 ks x 4 nt x 3 = 48 MMAs; Wh B-fragments in registers (64 regs).
// smem: h hi (16x1040B) | h lo | sD[8][16][68]f32 | csh[256]
// ---------------------------------------------------------------------------
#define HROW 1040
#define HBUF (16 * HROW)                    // 16,640
#define SD_OFF (2 * HBUF)                   // 33,280
#define SDS 68
#define CSH_OFF (SD_OFF + 8 * 16 * SDS * 4) // 68,096
#define SMEM_SCAN (CSH_OFF + 1024)          // 69,120

__global__ __launch_bounds__(512, 1) void lstm_scan_kernel(
    const float* __restrict__ c0, const float* __restrict__ h0,
    float* __restrict__ out)
{
    extern __shared__ __align__(16) char sm[];
    float* sD  = (float*)(sm + SD_OFF);
    float* csh = (float*)(sm + CSH_OFF);
    const uint32_t sbase = smem_u32(sm);

    const int bx = blockIdx.x;
    const int gu = bx >> 2;            // unit group 0..31 (16 units)
    const int bq = bx & 3;             // batch quarter 0..3 (16 batches)
    const int u_base = gu * 16;
    const int b_base = bq * 16;
    const int tid = threadIdx.x;
    const int lane = tid & 31;
    const int wid = tid >> 5;
    const int grp = lane >> 2;
    const int tig = lane & 3;
    const int nw = wid & 1;            // row half (32 gate rows)
    const int kq = wid >> 1;           // k slice (64 k: 32 in each unit-half)
    const int ab = tid >> 4;           // activation local batch 0..15 (tid<256)
    const int au = tid & 15;           // activation unit 0..15

    // ---- Wh B fragments -> registers (warp: 32 rows x 64 k) ----
    uint32_t bH[4][4][2], bL[4][4][2];
    {
        const __nv_bfloat16* baseH = g_whB_hi + (size_t)gu * 64 * 512;
        const __nv_bfloat16* baseL = g_whB_lo + (size_t)gu * 64 * 512;
#pragma unroll
        for (int ks = 0; ks < 4; ks++) {
            int kf = (ks < 2) ? (kq * 32 + ks * 16) : (256 + kq * 32 + (ks - 2) * 16);
            kf += tig * 2;
#pragma unroll
            for (int nt = 0; nt < 4; nt++) {
                int r = nw * 32 + nt * 8 + grp;
                bH[ks][nt][0] = *(const uint32_t*)(baseH + (size_t)r * 512 + kf);
                bH[ks][nt][1] = *(const uint32_t*)(baseH + (size_t)r * 512 + kf + 8);
                bL[ks][nt][0] = *(const uint32_t*)(baseL + (size_t)r * 512 + kf);
                bL[ks][nt][1] = *(const uint32_t*)(baseL + (size_t)r * 512 + kf + 8);
            }
        }
    }

    if (tid < 256) {
        int bg = b_base + ab;
        csh[tid] = c0[bg * HH + u_base + au];
        float hv = h0[bg * HH + u_base + au];
        __nv_bfloat16 hi = __float2bfloat16(hv);
        __nv_bfloat16 lo = __float2bfloat16(hv - __bfloat162float(hi));
        g_hb_hi[0][bg * HH + u_base + au] = hi;
        g_hb_lo[0][bg * HH + u_base + au] = lo;
    }
    unsigned bidx = 1;
    gbar(bidx++, bq, tid);

    float* ys = out + 2 * BATCH * HH;

    for (int s = 0; s < TT; s++) {
        const int ph = s & 1;

        float4 xw = make_float4(0.f, 0.f, 0.f, 0.f);
        if (tid < 256)
            xw = __ldg((const float4*)g_xwt +
                       ((((size_t)s * 32 + gu) * 64 + b_base + ab) * 16 + au));

        const char* hsH = (const char*)g_hb_hi[ph];
        const char* hsL = (const char*)g_hb_lo[ph];

        // half 0 (u<256): first 512B of this block's 16 batch rows (1 seg/thr)
        {
            int row = tid >> 5, sg = (tid & 31) * 16;
            size_t src = (size_t)(b_base + row) * 1024 + sg;
            CP_ASYNC16(sbase + row * HROW + sg,        hsH + src);
            CP_ASYNC16(sbase + HBUF + row * HROW + sg, hsL + src);
        }
        CP_COMMIT();
        // half 1 (u>=256)
        {
            int row = tid >> 5, sg = (tid & 31) * 16;
            size_t src = (size_t)(b_base + row) * 1024 + 512 + sg;
            CP_ASYNC16(sbase + row * HROW + 512 + sg,        hsH + src);
            CP_ASYNC16(sbase + HBUF + row * HROW + 512 + sg, hsL + src);
        }
        CP_COMMIT();

        float acc[4][4];   // [nt][q]
#pragma unroll
        for (int nt = 0; nt < 4; nt++)
#pragma unroll
            for (int q = 0; q < 4; q++) acc[nt][q] = 0.f;

        const char* bufH = sm;
        const char* bufL = sm + HBUF;

        CP_WAIT(1);            // half 0 landed
        __syncthreads();
#pragma unroll
        for (int ks = 0; ks < 2; ks++) {
            int col = (kq * 32 + ks * 16 + tig * 2) * 2;
            int aoff = grp * HROW + col;
            uint32_t ah0 = *(const uint32_t*)(bufH + aoff);
            uint32_t ah1 = *(const uint32_t*)(bufH + aoff + 8 * HROW);
            uint32_t ah2 = *(const uint32_t*)(bufH + aoff + 16);
            uint32_t ah3 = *(const uint32_t*)(bufH + aoff + 8 * HROW + 16);
            uint32_t al0 = *(const uint32_t*)(bufL + aoff);
            uint32_t al1 = *(const uint32_t*)(bufL + aoff + 8 * HROW);
            uint32_t al2 = *(const uint32_t*)(bufL + aoff + 16);
            uint32_t al3 = *(const uint32_t*)(bufL + aoff + 8 * HROW + 16);
#pragma unroll
            for (int nt = 0; nt < 4; nt++) {
                MMA_BF16(acc[nt], ah0, ah1, ah2, ah3, bH[ks][nt][0], bH[ks][nt][1]);
                MMA_BF16(acc[nt], al0, al1, al2, al3, bH[ks][nt][0], bH[ks][nt][1]);
                MMA_BF16(acc[nt], ah0, ah1, ah2, ah3, bL[ks][nt][0], bL[ks][nt][1]);
            }
        }
        CP_WAIT(0);            // half 1 landed
        __syncthreads();
#pragma unroll
        for (int ks = 2; ks < 4; ks++) {
            int col = (256 + kq * 32 + (ks - 2) * 16 + tig * 2) * 2;
            int aoff = grp * HROW + col;
            uint32_t ah0 = *(const uint32_t*)(bufH + aoff);
            uint32_t ah1 = *(const uint32_t*)(bufH + aoff + 8 * HROW);
            uint32_t ah2 = *(const uint32_t*)(bufH + aoff + 16);
            uint32_t ah3 = *(const uint32_t*)(bufH + aoff + 8 * HROW + 16);
            uint32_t al0 = *(const uint32_t*)(bufL + aoff);
            uint32_t al1 = *(const uint32_t*)(bufL + aoff + 8 * HROW);
            uint32_t al2 = *(const uint32_t*)(bufL + aoff + 16);
            uint32_t al3 = *(const uint32_t*)(bufL + aoff + 8 * HROW + 16);
#pragma unroll
            for (int nt = 0; nt < 4; nt++) {
                MMA_BF16(acc[nt], ah0, ah1, ah2, ah3, bH[ks][nt][0], bH[ks][nt][1]);
                MMA_BF16(acc[nt], al0, al1, al2, al3, bH[ks][nt][0], bH[ks][nt][1]);
                MMA_BF16(acc[nt], ah0, ah1, ah2, ah3, bL[ks][nt][0], bL[ks][nt][1]);
            }
        }

        // store D partials: sD[kq][b 16][r 64], row stride SDS
#pragma unroll
        for (int nt = 0; nt < 4; nt++) {
            int r = nw * 32 + nt * 8 + tig * 2;
            *(float2*)&sD[(kq * 16 + grp) * SDS + r] =
                make_float2(acc[nt][0], acc[nt][1]);
            *(float2*)&sD[(kq * 16 + grp + 8) * SDS + r] =
                make_float2(acc[nt][2], acc[nt][3]);
        }
        __syncthreads();

        if (tid < 256) {
            float si = xw.x, sf = xw.y, sg2 = xw.z, so = xw.w;
#pragma unroll
            for (int q = 0; q < 8; q++) {
                float4 s4 = *(float4*)&sD[(q * 16 + ab) * SDS + au * 4];
                si += s4.x; sf += s4.y; sg2 += s4.z; so += s4.w;
            }
            float ig = sigf(si);
            float fg = sigf(sf);
            float gg = tanhfast(sg2);
            float og = sigf(so);
            float cold = csh[tid];
            float cnew = fg * cold + ig * gg;
            float hnew = og * tanhfast(cnew);
            csh[tid] = cnew;

            int bg = b_base + ab;
            __nv_bfloat16 hi = __float2bfloat16(hnew);
            __nv_bfloat16 lo = __float2bfloat16(hnew - __bfloat162float(hi));
            int uo = bg * HH + u_base + au;
            g_hb_hi[ph ^ 1][uo] = hi;
            g_hb_lo[ph ^ 1][uo] = lo;

            ys[((size_t)bg * TT + s) * HH + u_base + au] = hnew;
            if (s == TT - 1) {
                out[bg * HH + u_base + au] = cnew;                 // cT
                out[BATCH * HH + bg * HH + u_base + au] = hnew;    // hT
            }
        }

        if (s < TT - 1) gbar(bidx++, bq, tid);
    }
}

// ---------------------------------------------------------------------------
extern "C" void kernel_launch(void* const* d_in, const int* in_sizes, int n_in,
                              void* d_out, int out_size) {
    const float* x    = (const float*)d_in[0];   // [64][1024][512]
    const float* c0   = (const float*)d_in[1];   // [64][512]
    const float* h0   = (const float*)d_in[2];   // [64][512]
    const float* Wi   = (const float*)d_in[3];   // [512][2048]
    const float* Wh   = (const float*)d_in[4];   // [512][2048]
    const float* bias = (const float*)d_in[5];   // [2048]
    float* out = (float*)d_out;                  // cT | hT | ys

    cudaFuncSetAttribute(lstm_scan_kernel,
                         cudaFuncAttributeMaxDynamicSharedMemorySize, SMEM_SCAN);
    cudaFuncSetAttribute(gemm_hmma_kernel,
                         cudaFuncAttributeMaxDynamicSharedMemorySize, SMEM_GEMM);

    pack_x_kernel<<<131072, 256>>>(x);
    pack_wi_kernel<<<4096, 256>>>(Wi);
    pack_whB_kernel<<<4096, 256>>>(Wh);
    reset_bar_kernel<<<1, 128>>>();
    gemm_hmma_kernel<<<dim3(16, 512), 256, SMEM_GEMM>>>(bias);
    lstm_scan_kernel<<<GRID_R, 512, SMEM_SCAN>>>(c0, h0, out);
}

// round 12
// speedup vs baseline: 1.4986x; 1.0540x over previous
#include <cuda_runtime.h>
#include <cuda_bf16.h>
#include <cstdint>

#define BATCH 64
#define TT 1024
#define DD 512
#define HH 512
#define J4 2048
#define GRID_R 128        // scan grid (<=148 SMs -> co-resident)

// Scratch (static device memory; no runtime allocation)
__device__ float g_xwt[(size_t)TT * 32 * 64 * 64];    // [t][gu][b][ut][g]   512 MB
__device__ __nv_bfloat16 g_xb_hi[(size_t)BATCH * TT * DD];  // X bf16 hi [m][k]  64 MB
__device__ __nv_bfloat16 g_xb_lo[(size_t)BATCH * TT * DD];  // X bf16 lo [m][k]  64 MB
__device__ __nv_bfloat16 g_wib_hi[(size_t)J4 * DD];   // [n][k] bf16 hi      2 MB
__device__ __nv_bfloat16 g_wib_lo[(size_t)J4 * DD];   // [n][k] bf16 lo      2 MB
__device__ __nv_bfloat16 g_whB_hi[(size_t)32 * 64 * 512];   // [gu][r][k]    2 MB
__device__ __nv_bfloat16 g_whB_lo[(size_t)32 * 64 * 512];   // [gu][r][k]    2 MB
__device__ __nv_bfloat16 g_hb_hi[2][BATCH * HH];      // h bf16 hi, [b][u]
__device__ __nv_bfloat16 g_hb_lo[2][BATCH * HH];      // h bf16 lo, [b][u]
__device__ unsigned g_pflag[4][32 * 32];              // [bq][gu*32] production count

// ---------------------------------------------------------------------------
__device__ __forceinline__ uint32_t smem_u32(const void* p) {
    uint32_t a;
    asm("{ .reg .u64 t; cvta.to.shared.u64 t, %1; cvt.u32.u64 %0, t; }"
        : "=r"(a) : "l"(p));
    return a;
}
#define CP_ASYNC16(dst, src) \
    asm volatile("cp.async.cg.shared.global [%0], [%1], 16;" :: "r"(dst), "l"(src))
#define CP_COMMIT()  asm volatile("cp.async.commit_group;" ::: "memory")
#define CP_WAIT(n)   asm volatile("cp.async.wait_group %0;" :: "n"(n) : "memory")

#define MMA_BF16(d, a0, a1, a2, a3, b0, b1)                                    \
    asm volatile("mma.sync.aligned.m16n8k16.row.col.f32.bf16.bf16.f32 "        \
                 "{%0,%1,%2,%3},{%4,%5,%6,%7},{%8,%9},{%0,%1,%2,%3};"          \
                 : "+f"((d)[0]), "+f"((d)[1]), "+f"((d)[2]), "+f"((d)[3])      \
                 : "r"(a0), "r"(a1), "r"(a2), "r"(a3), "r"(b0), "r"(b1))

__device__ __forceinline__ void st_rel(unsigned* p, unsigned v) {
    asm volatile("st.release.gpu.u32 [%0], %1;" :: "l"(p), "r"(v) : "memory");
}
__device__ __forceinline__ unsigned ld_acq(const unsigned* p) {
    unsigned v;
    asm volatile("ld.acquire.gpu.u32 %0, [%1];" : "=r"(v) : "l"(p) : "memory");
    return v;
}

// ---------------------------------------------------------------------------
__global__ void reset_bar_kernel() {
    ((unsigned*)g_pflag)[blockIdx.x * 256 + threadIdx.x] = 0u;
}

// X fp32 -> bf16 hi/lo split (same [m][k] layout)
__global__ void pack_x_kernel(const float* __restrict__ X) {
    size_t i = (size_t)blockIdx.x * 256 + threadIdx.x;
    float w = X[i];
    __nv_bfloat16 hi = __float2bfloat16(w);
    __nv_bfloat16 lo = __float2bfloat16(w - __bfloat162float(hi));
    g_xb_hi[i] = hi;
    g_xb_lo[i] = lo;
}

// Wi[k][n] -> bf16 hi/lo split, transposed [n][k]
__global__ void pack_wi_kernel(const float* __restrict__ Wi) {
    int i = blockIdx.x * 256 + threadIdx.x;
    int k = i & 511;
    int n = i >> 9;
    float w = Wi[(size_t)k * J4 + n];
    __nv_bfloat16 hi = __float2bfloat16(w);
    __nv_bfloat16 lo = __float2bfloat16(w - __bfloat162float(hi));
    g_wib_hi[i] = hi;
    g_wib_lo[i] = lo;
}

// Wh -> per-unit-group B rows: g_whB[gu][r=ut*4+g][k], gu has 16 units (64 rows)
__global__ void pack_whB_kernel(const float* __restrict__ Wh) {
    int i  = blockIdx.x * 256 + threadIdx.x;     // 1,048,576 total
    int k  = i & 511;
    int r  = (i >> 9) & 63;
    int gu = i >> 15;
    int ut = r >> 2, g = r & 3;
    float w = Wh[(size_t)k * J4 + g * 512 + gu * 16 + ut];
    __nv_bfloat16 hi = __float2bfloat16(w);
    __nv_bfloat16 lo = __float2bfloat16(w - __bfloat162float(hi));
    g_whB_hi[i] = hi;
    g_whB_lo[i] = lo;
}

// ---------------------------------------------------------------------------
// HMMA GEMM, cp.async double-buffered (proven): 128x128xK512 (BK=32), 8 warps.
// ---------------------------------------------------------------------------
#define RSTRIDE 80
#define ARR_SZ (128 * RSTRIDE)     // 10240
#define BUFG_SZ (4 * ARR_SZ)       // 40960
#define SMEM_GEMM (2 * BUFG_SZ)    // 81920

// m = b*1024 + t ; j = g*512 + u  ->  g_xwt[t][gu][b][ut][g]
__device__ __forceinline__ void st_xwt(int m, int j, float v) {
    int b = m >> 10, t = m & 1023, u = j & 511, g = j >> 9;
    int gu = u >> 4, ut = u & 15;
    g_xwt[((((size_t)t * 32 + gu) * 64 + b) * 16 + ut) * 4 + g] = v;
}

__global__ __launch_bounds__(256) void gemm_hmma_kernel(const float* __restrict__ bias)
{
    extern __shared__ __align__(16) char sm[];
    const uint32_t sbase = smem_u32(sm);

    const int nBase = blockIdx.x * 128;
    const int mBase = blockIdx.y * 128;
    const int tid = threadIdx.x;
    const int wid = tid >> 5;
    const int lane = tid & 31;
    const int wm = wid >> 2;
    const int wn = wid & 3;
    const int tig = lane & 3;
    const int grp = lane >> 2;

    float acc[4][4][4];
#pragma unroll
    for (int mt = 0; mt < 4; mt++)
#pragma unroll
        for (int nt = 0; nt < 4; nt++)
#pragma unroll
            for (int q = 0; q < 4; q++) acc[mt][nt][q] = 0.f;

    const int s0 = tid * 2;

#define FILL_CHUNK(buf, ch) do {                                               \
    int k0 = (ch) * 32;                                                        \
    uint32_t db = sbase + (buf) * BUFG_SZ;                                     \
    _Pragma("unroll")                                                          \
    for (int q = 0; q < 2; q++) {                                              \
        int s2 = s0 + q;                                                       \
        int row = s2 >> 2, sg = s2 & 3;                                        \
        uint32_t doff = row * RSTRIDE + sg * 16;                               \
        size_t asrc = ((size_t)(mBase + row) * 512 + k0 + sg * 8) * 2;         \
        size_t bsrc = ((size_t)(nBase + row) * 512 + k0 + sg * 8) * 2;         \
        CP_ASYNC16(db + doff,              (const char*)g_xb_hi + asrc);       \
        CP_ASYNC16(db + ARR_SZ + doff,     (const char*)g_xb_lo + asrc);       \
        CP_ASYNC16(db + 2 * ARR_SZ + doff, (const char*)g_wib_hi + bsrc);      \
        CP_ASYNC16(db + 3 * ARR_SZ + doff, (const char*)g_wib_lo + bsrc);      \
    }                                                                          \
} while (0)

    FILL_CHUNK(0, 0);
    CP_COMMIT();

    for (int ch = 0; ch < 16; ch++) {
        if (ch < 15) {
            FILL_CHUNK((ch + 1) & 1, ch + 1);
            CP_COMMIT();
            CP_WAIT(1);
        } else {
            CP_WAIT(0);
        }
        __syncthreads();

        const char* smAH = sm + (ch & 1) * BUFG_SZ;
        const char* smAL = smAH + ARR_SZ;
        const char* smBH = smAH + 2 * ARR_SZ;
        const char* smBL = smAH + 3 * ARR_SZ;

#pragma unroll
        for (int ks = 0; ks < 2; ks++) {
            const int kb = ks * 16;
            uint32_t bhf[4][2], blf[4][2];
#pragma unroll
            for (int nt = 0; nt < 4; nt++) {
                int row = wn * 32 + nt * 8 + grp;
                int boff = row * RSTRIDE + (kb + tig * 2) * 2;
                bhf[nt][0] = *(uint32_t*)(smBH + boff);
                bhf[nt][1] = *(uint32_t*)(smBH + boff + 16);
                blf[nt][0] = *(uint32_t*)(smBL + boff);
                blf[nt][1] = *(uint32_t*)(smBL + boff + 16);
            }
#pragma unroll
            for (int mt = 0; mt < 4; mt++) {
                int row = wm * 64 + mt * 16 + grp;
                int a0o = row * RSTRIDE + (kb + tig * 2) * 2;
                int a1o = a0o + 8 * RSTRIDE;
                uint32_t ah0 = *(uint32_t*)(smAH + a0o);
                uint32_t ah1 = *(uint32_t*)(smAH + a1o);
                uint32_t ah2 = *(uint32_t*)(smAH + a0o + 16);
                uint32_t ah3 = *(uint32_t*)(smAH + a1o + 16);
                uint32_t al0 = *(uint32_t*)(smAL + a0o);
                uint32_t al1 = *(uint32_t*)(smAL + a1o);
                uint32_t al2 = *(uint32_t*)(smAL + a0o + 16);
                uint32_t al3 = *(uint32_t*)(smAL + a1o + 16);
#pragma unroll
                for (int nt = 0; nt < 4; nt++) {
                    MMA_BF16(acc[mt][nt], ah0, ah1, ah2, ah3, bhf[nt][0], bhf[nt][1]);
                    MMA_BF16(acc[mt][nt], al0, al1, al2, al3, bhf[nt][0], bhf[nt][1]);
                    MMA_BF16(acc[mt][nt], ah0, ah1, ah2, ah3, blf[nt][0], blf[nt][1]);
                }
            }
        }
        __syncthreads();
    }

#pragma unroll
    for (int nt = 0; nt < 4; nt++) {
        int j0 = nBase + wn * 32 + nt * 8 + tig * 2;
        float bb0 = __ldg(&bias[j0]);
        float bb1 = __ldg(&bias[j0 + 1]);
#pragma unroll
        for (int mt = 0; mt < 4; mt++) {
            int m0 = mBase + wm * 64 + mt * 16 + grp;
            st_xwt(m0,     j0,     acc[mt][nt][0] + bb0);
            st_xwt(m0,     j0 + 1, acc[mt][nt][1] + bb1);
            st_xwt(m0 + 8, j0,     acc[mt][nt][2] + bb0);
            st_xwt(m0 + 8, j0 + 1, acc[mt][nt][3] + bb1);
        }
    }
}

// ---------------------------------------------------------------------------
__device__ __forceinline__ float sigf(float x) {
    return 1.0f / (1.0f + __expf(-x));
}
__device__ __forceinline__ float tanhfast(float x) {
    float e = __expf(2.0f * x);
    return 1.0f - 2.0f / (e + 1.0f);
}

// ---------------------------------------------------------------------------
// HMMA persistent scan, dataflow-synchronized: 128 blocks = 32 unit-groups x 4
// batch-quarters. No central barrier: each block publishes a production flag;
// each loader warp (nw==0 of a kq pair) acquire-polls only its 4 producers
// (gu = 2kq, 2kq+1, 16+2kq, 16+2kq+1), then cp.asyncs its 4KB h slice.
// Block-level skew stays <=1 step (a block's 8 warp pairs collectively wait on
// all 32 flags each step), so double buffers (smem h, global h) are race-free.
// 512 threads = 16 warps = 2 nw x 8 kq. Per warp: 4ks x 4nt x 3 = 48 MMAs.
// smem: hbuf[2 parities][hi|lo 16x1040B] | sD[8][16][68]f32 | csh[256]
// ---------------------------------------------------------------------------
#define HROW 1040
#define HBUF (16 * HROW)                    // 16,640
#define BUF2 (2 * HBUF)                     // hi+lo for one parity: 33,280
#define SD_OFF (2 * BUF2)                   // 66,560
#define SDS 68
#define CSH_OFF (SD_OFF + 8 * 16 * SDS * 4) // 101,376
#define SMEM_SCAN (CSH_OFF + 1024)          // 102,400

__global__ __launch_bounds__(512, 1) void lstm_scan_kernel(
    const float* __restrict__ c0, const float* __restrict__ h0,
    float* __restrict__ out)
{
    extern __shared__ __align__(16) char sm[];
    float* sD  = (float*)(sm + SD_OFF);
    float* csh = (float*)(sm + CSH_OFF);
    const uint32_t sbase = smem_u32(sm);

    const int bx = blockIdx.x;
    const int gu = bx >> 2;            // unit group 0..31 (16 units)
    const int bq = bx & 3;             // batch quarter 0..3 (16 batches)
    const int u_base = gu * 16;
    const int b_base = bq * 16;
    const int tid = threadIdx.x;
    const int lane = tid & 31;
    const int wid = tid >> 5;
    const int grp = lane >> 2;
    const int tig = lane & 3;
    const int nw = wid & 1;            // row half (32 gate rows)
    const int kq = wid >> 1;           // k slice (2x32 units)
    const int ab = tid >> 4;           // activation local batch 0..15 (tid<256)
    const int au = tid & 15;           // activation unit 0..15

    // ---- Wh B fragments -> registers (warp: 32 rows x 64 k) ----
    uint32_t bH[4][4][2], bL[4][4][2];
    {
        const __nv_bfloat16* baseH = g_whB_hi + (size_t)gu * 64 * 512;
        const __nv_bfloat16* baseL = g_whB_lo + (size_t)gu * 64 * 512;
#pragma unroll
        for (int ks = 0; ks < 4; ks++) {
            int kf = (ks < 2) ? (kq * 32 + ks * 16) : (256 + kq * 32 + (ks - 2) * 16);
            kf += tig * 2;
#pragma unroll
            for (int nt = 0; nt < 4; nt++) {
                int r = nw * 32 + nt * 8 + grp;
                bH[ks][nt][0] = *(const uint32_t*)(baseH + (size_t)r * 512 + kf);
                bH[ks][nt][1] = *(const uint32_t*)(baseH + (size_t)r * 512 + kf + 8);
                bL[ks][nt][0] = *(const uint32_t*)(baseL + (size_t)r * 512 + kf);
                bL[ks][nt][1] = *(const uint32_t*)(baseL + (size_t)r * 512 + kf + 8);
            }
        }
    }

    if (tid < 256) {
        int bg = b_base + ab;
        csh[tid] = c0[bg * HH + u_base + au];
        float hv = h0[bg * HH + u_base + au];
        __nv_bfloat16 hi = __float2bfloat16(hv);
        __nv_bfloat16 lo = __float2bfloat16(hv - __bfloat162float(hi));
        g_hb_hi[0][bg * HH + u_base + au] = hi;
        g_hb_lo[0][bg * HH + u_base + au] = lo;
    }
    __syncthreads();
    if (tid == 0) {
        __threadfence();
        st_rel(&g_pflag[bq][gu * 32], 1u);    // production #0 (init) done
    }

    float* ys = out + 2 * BATCH * HH;

    for (int s = 0; s < TT; s++) {
        const int ph = s & 1;

        float4 xw = make_float4(0.f, 0.f, 0.f, 0.f);
        if (tid < 256)
            xw = __ldg((const float4*)g_xwt +
                       ((((size_t)s * 32 + gu) * 64 + b_base + ab) * 16 + au));

        // ---- loader warp: poll 4 producers, fetch 4KB slice ----
        if (nw == 0) {
            if (lane < 4) {
                int pg = 2 * kq + (lane & 1) + ((lane >> 1) << 4);
                const unsigned* f = &g_pflag[bq][pg * 32];
                while (ld_acq(f) < (unsigned)(s + 1)) __nanosleep(20);
            }
            __syncwarp();
            const char* srcH = (const char*)g_hb_hi[ph];
            const char* srcL = (const char*)g_hb_lo[ph];
            uint32_t dbase = sbase + (s & 1) * BUF2;
#pragma unroll
            for (int q = 0; q < 8; q++) {
                int idx = q * 32 + lane;      // 0..255
                int row = idx & 15;
                int rest = idx >> 4;          // 0..15
                int hl = rest & 1;
                int half = (rest >> 1) & 1;
                int seg = rest >> 2;          // 0..3
                uint32_t off = row * HROW + half * 512 + kq * 64 + seg * 16;
                size_t src = (size_t)(b_base + row) * 1024 + half * 512 + kq * 64 + seg * 16;
                CP_ASYNC16(dbase + hl * HBUF + off, (hl ? srcL : srcH) + src);
            }
            CP_COMMIT();
            CP_WAIT(0);
        }
        // pair barrier: loader's smem writes visible to partner warp
        asm volatile("bar.sync %0, %1;" :: "r"(kq + 1), "r"(64) : "memory");

        float acc[4][4];   // [nt][q]
#pragma unroll
        for (int nt = 0; nt < 4; nt++)
#pragma unroll
            for (int q = 0; q < 4; q++) acc[nt][q] = 0.f;

        const char* bufH = sm + (s & 1) * BUF2;
        const char* bufL = bufH + HBUF;

#pragma unroll
        for (int ks = 0; ks < 4; ks++) {
            int col = (ks < 2) ? ((kq * 32 + ks * 16 + tig * 2) * 2)
                               : ((256 + kq * 32 + (ks - 2) * 16 + tig * 2) * 2);
            int aoff = grp * HROW + col;
            uint32_t ah0 = *(const uint32_t*)(bufH + aoff);
            uint32_t ah1 = *(const uint32_t*)(bufH + aoff + 8 * HROW);
            uint32_t ah2 = *(const uint32_t*)(bufH + aoff + 16);
            uint32_t ah3 = *(const uint32_t*)(bufH + aoff + 8 * HROW + 16);
            uint32_t al0 = *(const uint32_t*)(bufL + aoff);
            uint32_t al1 = *(const uint32_t*)(bufL + aoff + 8 * HROW);
            uint32_t al2 = *(const uint32_t*)(bufL + aoff + 16);
            uint32_t al3 = *(const uint32_t*)(bufL + aoff + 8 * HROW + 16);
#pragma unroll
            for (int nt = 0; nt < 4; nt++) {
                MMA_BF16(acc[nt], ah0, ah1, ah2, ah3, bH[ks][nt][0], bH[ks][nt][1]);
                MMA_BF16(acc[nt], al0, al1, al2, al3, bH[ks][nt][0], bH[ks][nt][1]);
                MMA_BF16(acc[nt], ah0, ah1, ah2, ah3, bL[ks][nt][0], bL[ks][nt][1]);
            }
        }

        // store D partials: sD[kq][b 16][r 64]
#pragma unroll
        for (int nt = 0; nt < 4; nt++) {
            int r = nw * 32 + nt * 8 + tig * 2;
            *(float2*)&sD[(kq * 16 + grp) * SDS + r] =
                make_float2(acc[nt][0], acc[nt][1]);
            *(float2*)&sD[(kq * 16 + grp + 8) * SDS + r] =
                make_float2(acc[nt][2], acc[nt][3]);
        }
        __syncthreads();

        if (tid < 256) {
            float si = xw.x, sf = xw.y, sg2 = xw.z, so = xw.w;
#pragma unroll
            for (int q = 0; q < 8; q++) {
                float4 s4 = *(float4*)&sD[(q * 16 + ab) * SDS + au * 4];
                si += s4.x; sf += s4.y; sg2 += s4.z; so += s4.w;
            }
            float ig = sigf(si);
            float fg = sigf(sf);
            float gg = tanhfast(sg2);
            float og = sigf(so);
            float cold = csh[tid];
            float cnew = fg * cold + ig * gg;
            float hnew = og * tanhfast(cnew);
            csh[tid] = cnew;

            int bg = b_base + ab;
            __nv_bfloat16 hi = __float2bfloat16(hnew);
            __nv_bfloat16 lo = __float2bfloat16(hnew - __bfloat162float(hi));
            int uo = bg * HH + u_base + au;
            g_hb_hi[ph ^ 1][uo] = hi;
            g_hb_lo[ph ^ 1][uo] = lo;

            ys[((size_t)bg * TT + s) * HH + u_base + au] = hnew;
            if (s == TT - 1) {
                out[bg * HH + u_base + au] = cnew;                 // cT
                out[BATCH * HH + bg * HH + u_base + au] = hnew;    // hT
            }
        }
        __syncthreads();
        if (s < TT - 1 && tid == 0) {
            __threadfence();
            st_rel(&g_pflag[bq][gu * 32], (unsigned)(s + 2));
        }
    }
}

// ---------------------------------------------------------------------------
extern "C" void kernel_launch(void* const* d_in, const int* in_sizes, int n_in,
                              void* d_out, int out_size) {
    const float* x    = (const float*)d_in[0];   // [64][1024][512]
    const float* c0   = (const float*)d_in[1];   // [64][512]
    const float* h0   = (const float*)d_in[2];   // [64][512]
    const float* Wi   = (const float*)d_in[3];   // [512][2048]
    const float* Wh   = (const float*)d_in[4];   // [512][2048]
    const float* bias = (const float*)d_in[5];   // [2048]
    float* out = (float*)d_out;                  // cT | hT | ys

    cudaFuncSetAttribute(lstm_scan_kernel,
                         cudaFuncAttributeMaxDynamicSharedMemorySize, SMEM_SCAN);
    cudaFuncSetAttribute(gemm_hmma_kernel,
                         cudaFuncAttributeMaxDynamicSharedMemorySize, SMEM_GEMM);

    pack_x_kernel<<<131072, 256>>>(x);
    pack_wi_kernel<<<4096, 256>>>(Wi);
    pack_whB_kernel<<<4096, 256>>>(Wh);
    reset_bar_kernel<<<16, 256>>>();
    gemm_hmma_kernel<<<dim3(16, 512), 256, SMEM_GEMM>>>(bias);
    lstm_scan_kernel<<<GRID_R, 512, SMEM_SCAN>>>(c0, h0, out);
}